// round 1
// baseline (speedup 1.0000x reference)
#include <cuda_runtime.h>
#include <math.h>

#define DCH   64          // D
#define EDIM  64          // E_DIM
#define FAN   192         // 2*D + E_DIM
#define TILE_E 128
#define TILE_N 128        // 2*D outputs (interleaved gate/val)
#define KBLK  16
#define SPAD  4
#define AS_STRIDE (TILE_E + SPAD)  // 132
#define BS_STRIDE (TILE_N + SPAD)  // 132

#define MAX_NODES 50176

__device__ float g_message[MAX_NODES * DCH];
__device__ float g_sum[DCH];
__device__ float g_sumsq[DCH];

// ---------- packed f32x2 helpers ----------
__device__ __forceinline__ void fma2(unsigned long long& c, unsigned long long a, unsigned long long b) {
    asm("fma.rn.f32x2 %0, %1, %2, %3;" : "=l"(c) : "l"(a), "l"(b), "l"(c));
}
__device__ __forceinline__ unsigned long long dup2(float a) {
    unsigned long long r;
    asm("mov.b64 %0, {%1, %1};" : "=l"(r) : "f"(a));
    return r;
}
__device__ __forceinline__ float2 unpack2(unsigned long long v) {
    float2 r;
    asm("mov.b64 {%0, %1}, %2;" : "=f"(r.x), "=f"(r.y) : "l"(v));
    return r;
}

__device__ __forceinline__ float softplus_f(float v) {
    return fmaxf(v, 0.0f) + log1pf(expf(-fabsf(v)));
}

// ---------- pass 0: zero scratch ----------
__global__ void zero_kernel(int total) {
    int i = blockIdx.x * blockDim.x + threadIdx.x;
    int stride = gridDim.x * blockDim.x;
    for (int j = i; j < total; j += stride) g_message[j] = 0.0f;
    if (i < DCH) { g_sum[i] = 0.0f; g_sumsq[i] = 0.0f; }
}

// ---------- pass 1: fused gather + GEMM + activations + scatter ----------
// Z[e, 0:64]   = x[src[e]]
// Z[e, 64:128] = x[tgt[e]]
// Z[e,128:192] = edge_attr[e]
// B columns interleaved: n=2d -> Wf[d][k], n=2d+1 -> Ws[d][k]
// Thread (tx,ty): tx in [0,16) owns d = tx*4 .. tx*4+3 (4 float2 pairs),
//                 ty in [0,16) owns edges ty*8 .. ty*8+7.
__global__ __launch_bounds__(256)
void edge_kernel(const float* __restrict__ x,
                 const float* __restrict__ ea,
                 const float* __restrict__ Wf,
                 const float* __restrict__ bf,
                 const float* __restrict__ Ws,
                 const float* __restrict__ bs,
                 const int*   __restrict__ esrc,
                 const int*   __restrict__ etgt,
                 int n_edges)
{
    __shared__ float Zs[KBLK][AS_STRIDE];
    __shared__ float Bs[KBLK][BS_STRIDE];
    __shared__ int s_src[TILE_E];
    __shared__ int s_tgt[TILE_E];

    const int tid = threadIdx.x;
    const int tx = tid & 15;
    const int ty = tid >> 4;
    const int e0 = blockIdx.x * TILE_E;

    // load edge indices for this tile
    for (int i = tid; i < TILE_E; i += 256) {
        int ge = e0 + i;
        s_src[i] = (ge < n_edges) ? esrc[ge] : 0;
        s_tgt[i] = (ge < n_edges) ? etgt[ge] : 0;
    }
    __syncthreads();

    unsigned long long acc[8][4];
    #pragma unroll
    for (int e = 0; e < 8; e++)
        #pragma unroll
        for (int p = 0; p < 4; p++) acc[e][p] = 0ULL;

    #pragma unroll
    for (int kb = 0; kb < FAN; kb += KBLK) {
        // ---- load Z tile: 128 edges x 16 k  (2048 elems, 8 per thread) ----
        #pragma unroll
        for (int j = 0; j < 8; j++) {
            int idx = tid + j * 256;
            int k = idx & 15;
            int e = idx >> 4;
            int kk = kb + k;
            int ge = e0 + e;
            float v = 0.0f;
            if (ge < n_edges) {
                if (kk < DCH)            v = x[s_src[e] * DCH + kk];
                else if (kk < 2 * DCH)   v = x[s_tgt[e] * DCH + (kk - DCH)];
                else                     v = ea[(long long)ge * EDIM + (kk - 2 * DCH)];
            }
            Zs[k][e] = v;
        }
        // ---- load W tile: 16 k x 128 n (interleaved Wf/Ws) ----
        #pragma unroll
        for (int j = 0; j < 8; j++) {
            int idx = tid + j * 256;
            int k = idx & 15;
            int n = idx >> 4;
            int d = n >> 1;
            int kk = kb + k;
            const float* w = (n & 1) ? Ws : Wf;
            Bs[k][n] = w[d * FAN + kk];
        }
        __syncthreads();

        // ---- 8x8 register microtile via packed fma.rn.f32x2 ----
        #pragma unroll
        for (int k = 0; k < KBLK; k++) {
            ulonglong2 b01 = *(const ulonglong2*)&Bs[k][tx * 8];
            ulonglong2 b23 = *(const ulonglong2*)&Bs[k][tx * 8 + 4];
            unsigned long long b[4] = {b01.x, b01.y, b23.x, b23.y};
            float4 a03 = *(const float4*)&Zs[k][ty * 8];
            float4 a47 = *(const float4*)&Zs[k][ty * 8 + 4];
            float av[8] = {a03.x, a03.y, a03.z, a03.w, a47.x, a47.y, a47.z, a47.w};
            #pragma unroll
            for (int e = 0; e < 8; e++) {
                unsigned long long ad = dup2(av[e]);
                #pragma unroll
                for (int p = 0; p < 4; p++) fma2(acc[e][p], ad, b[p]);
            }
        }
        __syncthreads();
    }

    // ---- epilogue: bias + sigmoid/softplus + gated product + scatter ----
    const int d0 = tx * 4;
    float bfv[4], bsv[4];
    #pragma unroll
    for (int p = 0; p < 4; p++) { bfv[p] = bf[d0 + p]; bsv[p] = bs[d0 + p]; }

    #pragma unroll
    for (int e = 0; e < 8; e++) {
        int le = ty * 8 + e;
        int ge = e0 + le;
        if (ge >= n_edges) continue;
        float m[4];
        #pragma unroll
        for (int p = 0; p < 4; p++) {
            float2 gv = unpack2(acc[e][p]);
            float g = gv.x + bfv[p];
            float v = gv.y + bsv[p];
            float gate = 1.0f / (1.0f + expf(-g));
            float val  = softplus_f(v);
            m[p] = gate * val;
        }
        float* dst = &g_message[(long long)s_src[le] * DCH + d0];
        asm volatile("red.global.add.v4.f32 [%0], {%1, %2, %3, %4};"
                     :: "l"(dst), "f"(m[0]), "f"(m[1]), "f"(m[2]), "f"(m[3])
                     : "memory");
    }
}

// ---------- pass 2: per-channel sum / sumsq over nodes ----------
__global__ void stats_kernel(int n_nodes) {
    int c = threadIdx.x & 63;
    int r = threadIdx.x >> 6;   // 0..3 (256 threads)
    float s = 0.0f, q = 0.0f;
    for (int i = blockIdx.x * 4 + r; i < n_nodes; i += gridDim.x * 4) {
        float v = g_message[i * DCH + c];
        s += v;
        q += v * v;
    }
    __shared__ float sh_s[4][64];
    __shared__ float sh_q[4][64];
    sh_s[r][c] = s;
    sh_q[r][c] = q;
    __syncthreads();
    if (r == 0) {
        s = sh_s[0][c] + sh_s[1][c] + sh_s[2][c] + sh_s[3][c];
        q = sh_q[0][c] + sh_q[1][c] + sh_q[2][c] + sh_q[3][c];
        atomicAdd(&g_sum[c], s);
        atomicAdd(&g_sumsq[c], q);
    }
}

// ---------- pass 3: BN + residual + softplus ----------
__global__ void final_kernel(const float* __restrict__ x,
                             const float* __restrict__ gamma,
                             const float* __restrict__ beta,
                             float* __restrict__ out,
                             int total, float inv_n)
{
    int i = blockIdx.x * blockDim.x + threadIdx.x;
    if (i >= total) return;
    int c = i & 63;
    float mean = g_sum[c] * inv_n;
    float var  = g_sumsq[c] * inv_n - mean * mean;
    float inv_std = rsqrtf(var + 1e-5f);
    float mnorm = (g_message[i] - mean) * inv_std * gamma[c] + beta[c];
    float t = x[i] + mnorm;
    out[i] = softplus_f(t);
}

extern "C" void kernel_launch(void* const* d_in, const int* in_sizes, int n_in,
                              void* d_out, int out_size)
{
    const float* x     = (const float*)d_in[0];
    const float* ea    = (const float*)d_in[1];
    const float* Wf    = (const float*)d_in[2];
    const float* bf    = (const float*)d_in[3];
    const float* Ws    = (const float*)d_in[4];
    const float* bs    = (const float*)d_in[5];
    const float* gamma = (const float*)d_in[6];
    const float* beta  = (const float*)d_in[7];
    const int*   esrc  = (const int*)d_in[8];
    const int*   etgt  = (const int*)d_in[9];
    float* out = (float*)d_out;

    int n_nodes = in_sizes[0] / DCH;
    int n_edges = in_sizes[8];
    int total   = n_nodes * DCH;

    // pass 0: zero scratch
    {
        int grid = (total + 255) / 256;
        if (grid > 1024) grid = 1024;
        zero_kernel<<<grid, 256>>>(total);
    }
    // pass 1: edge GEMM + scatter
    {
        int grid = (n_edges + TILE_E - 1) / TILE_E;
        edge_kernel<<<grid, 256>>>(x, ea, Wf, bf, Ws, bs, esrc, etgt, n_edges);
    }
    // pass 2: BN stats
    stats_kernel<<<148, 256>>>(n_nodes);
    // pass 3: BN + softplus
    {
        int grid = (total + 255) / 256;
        final_kernel<<<grid, 256>>>(x, gamma, beta, out, total, 1.0f / (float)n_nodes);
    }
}

// round 2
// speedup vs baseline: 2.7406x; 2.7406x over previous
#include <cuda_runtime.h>
#include <math.h>

#define DCH    64
#define EDIM   64
#define FAN    192
#define TILE_E 128
#define KTOT   64
#define STRB   132        // Bs row stride (floats)
#define MAX_NODES 50176

__device__ float g_message[MAX_NODES * DCH];
__device__ float g_P1[MAX_NODES * 2 * DCH];   // interleaved (gate,val) pairs, src-side proj
__device__ float g_P2[MAX_NODES * 2 * DCH];   // tgt-side proj
__device__ float g_sum[DCH];
__device__ float g_sumsq[DCH];

// dynamic smem sizes (bytes)
#define SM_B_FLOATS   (KTOT * STRB)          // 8448
#define SM_Z_FLOATS   (KTOT * 128)           // 8192
#define EDGE_SMEM_BYTES ((SM_B_FLOATS + SM_Z_FLOATS) * 4 + 2 * TILE_E * 4)  // 67584
#define NODE_SMEM_BYTES ((SM_B_FLOATS + SM_Z_FLOATS) * 4)                   // 66560

// ---------- packed f32x2 helpers ----------
__device__ __forceinline__ void fma2(unsigned long long& c, unsigned long long a, unsigned long long b) {
    asm("fma.rn.f32x2 %0, %1, %2, %3;" : "=l"(c) : "l"(a), "l"(b), "l"(c));
}
__device__ __forceinline__ unsigned long long dup2(float a) {
    unsigned long long r;
    asm("mov.b64 %0, {%1, %1};" : "=l"(r) : "f"(a));
    return r;
}
__device__ __forceinline__ float2 unpack2(unsigned long long v) {
    float2 r;
    asm("mov.b64 {%0, %1}, %2;" : "=f"(r.x), "=f"(r.y) : "l"(v));
    return r;
}
__device__ __forceinline__ float softplus_f(float v) {
    return fmaxf(v, 0.0f) + log1pf(expf(-fabsf(v)));
}

// B physical layout per k-row (128 floats):
//   phys = c*64 + tx*4 + j2   (c = chunk 0/1, tx = owner thread, j2 = 0..3)
//   logical pair d = tx*4 + c*2 + (j2>>1), gate/val = j2&1
// Thread tx reads two conflict-free float4s: [tx*4] and [64 + tx*4].
// acc pair p (0..3) corresponds to d = tx*4 + p.
__device__ __forceinline__ void fill_B(float* Bs, const float* __restrict__ Wf,
                                       const float* __restrict__ Ws, int kofs, int tid)
{
    #pragma unroll
    for (int j = 0; j < 32; j++) {
        int idx = tid + j * 256;
        int k = idx >> 7;
        int phys = idx & 127;
        int c  = phys >> 6;
        int r  = phys & 63;
        int tx = r >> 2;
        int j2 = r & 3;
        int d  = tx * 4 + c * 2 + (j2 >> 1);
        int gv = j2 & 1;
        const float* w = gv ? Ws : Wf;
        Bs[k * STRB + phys] = w[d * FAN + kofs + k];
    }
}

// ---------- pass 0: zero scratch ----------
__global__ void zero_kernel(int total) {
    int i = blockIdx.x * blockDim.x + threadIdx.x;
    int stride = gridDim.x * blockDim.x;
    for (int j = i; j < total; j += stride) g_message[j] = 0.0f;
    if (i < DCH) { g_sum[i] = 0.0f; g_sumsq[i] = 0.0f; }
}

// ---------- pass 1: node projections  P = x @ Wslice.T (interleaved gate/val) ----------
__global__ __launch_bounds__(256, 2)
void node_proj_kernel(const float* __restrict__ x,
                      const float* __restrict__ Wf,
                      const float* __restrict__ Ws,
                      int n_nodes)
{
    extern __shared__ float sm[];
    float* Bs = sm;
    float* Zs = sm + SM_B_FLOATS;

    const int tid = threadIdx.x;
    const int tx = tid & 15;
    const int ty = tid >> 4;
    const int n0 = blockIdx.x * 128;
    const int wsel = blockIdx.y;            // 0 -> P1 (W cols 0..63), 1 -> P2 (64..127)
    float* P = wsel ? g_P2 : g_P1;

    fill_B(Bs, Wf, Ws, wsel * 64, tid);

    // X tile: Zs[k][(n + 4k)&127], rows coalesced from gmem
    #pragma unroll
    for (int j = 0; j < 32; j++) {
        int idx = tid + j * 256;
        int k = idx & 63;
        int n = idx >> 6;
        float v = (n0 + n < n_nodes) ? x[(n0 + n) * DCH + k] : 0.0f;
        Zs[k * 128 + ((n + 4 * k) & 127)] = v;
    }
    __syncthreads();

    unsigned long long acc[8][4];
    #pragma unroll
    for (int e = 0; e < 8; e++)
        #pragma unroll
        for (int p = 0; p < 4; p++) acc[e][p] = 0ULL;

    #pragma unroll 4
    for (int k = 0; k < KTOT; k++) {
        const float* bro = Bs + k * STRB;
        ulonglong2 c0 = *(const ulonglong2*)(bro + tx * 4);
        ulonglong2 c1 = *(const ulonglong2*)(bro + 64 + tx * 4);
        unsigned long long b[4] = {c0.x, c0.y, c1.x, c1.y};
        int col0 = (ty * 8 + 4 * k) & 127;
        int col1 = (ty * 8 + 4 + 4 * k) & 127;
        float4 a03 = *(const float4*)(Zs + k * 128 + col0);
        float4 a47 = *(const float4*)(Zs + k * 128 + col1);
        float av[8] = {a03.x, a03.y, a03.z, a03.w, a47.x, a47.y, a47.z, a47.w};
        #pragma unroll
        for (int e = 0; e < 8; e++) {
            unsigned long long ad = dup2(av[e]);
            #pragma unroll
            for (int p = 0; p < 4; p++) fma2(acc[e][p], ad, b[p]);
        }
    }

    #pragma unroll
    for (int e = 0; e < 8; e++) {
        int n = n0 + ty * 8 + e;
        if (n >= n_nodes) continue;
        float2 v0 = unpack2(acc[e][0]);
        float2 v1 = unpack2(acc[e][1]);
        float2 v2 = unpack2(acc[e][2]);
        float2 v3 = unpack2(acc[e][3]);
        float4* dst = (float4*)(P + n * 128 + tx * 8);
        dst[0] = make_float4(v0.x, v0.y, v1.x, v1.y);
        dst[1] = make_float4(v2.x, v2.y, v3.x, v3.y);
    }
}

// ---------- pass 2: edge GEMM (ea @ W3.T) + node proj gather + activations + scatter ----------
__global__ __launch_bounds__(256, 2)
void edge_kernel(const float* __restrict__ ea,
                 const float* __restrict__ Wf,
                 const float* __restrict__ bf,
                 const float* __restrict__ Ws,
                 const float* __restrict__ bs,
                 const int*   __restrict__ esrc,
                 const int*   __restrict__ etgt,
                 int n_edges)
{
    extern __shared__ float sm[];
    float* Bs = sm;
    float* Zs = sm + SM_B_FLOATS;
    int* s_src = (int*)(Zs + SM_Z_FLOATS);
    int* s_tgt = s_src + TILE_E;

    const int tid = threadIdx.x;
    const int tx = tid & 15;
    const int ty = tid >> 4;
    const int e0 = blockIdx.x * TILE_E;

    fill_B(Bs, Wf, Ws, 128, tid);   // W cols 128..191 (edge_attr slice)

    // Z tile from edge_attr, rotated layout
    #pragma unroll
    for (int j = 0; j < 32; j++) {
        int idx = tid + j * 256;
        int k = idx & 63;
        int e = idx >> 6;
        int ge = e0 + e;
        float v = (ge < n_edges) ? ea[(long long)ge * EDIM + k] : 0.0f;
        Zs[k * 128 + ((e + 4 * k) & 127)] = v;
    }
    for (int i = tid; i < TILE_E; i += 256) {
        int ge = e0 + i;
        s_src[i] = (ge < n_edges) ? esrc[ge] : 0;
        s_tgt[i] = (ge < n_edges) ? etgt[ge] : 0;
    }
    __syncthreads();

    unsigned long long acc[8][4];
    #pragma unroll
    for (int e = 0; e < 8; e++)
        #pragma unroll
        for (int p = 0; p < 4; p++) acc[e][p] = 0ULL;

    #pragma unroll 4
    for (int k = 0; k < KTOT; k++) {
        const float* bro = Bs + k * STRB;
        ulonglong2 c0 = *(const ulonglong2*)(bro + tx * 4);
        ulonglong2 c1 = *(const ulonglong2*)(bro + 64 + tx * 4);
        unsigned long long b[4] = {c0.x, c0.y, c1.x, c1.y};
        int col0 = (ty * 8 + 4 * k) & 127;
        int col1 = (ty * 8 + 4 + 4 * k) & 127;
        float4 a03 = *(const float4*)(Zs + k * 128 + col0);
        float4 a47 = *(const float4*)(Zs + k * 128 + col1);
        float av[8] = {a03.x, a03.y, a03.z, a03.w, a47.x, a47.y, a47.z, a47.w};
        #pragma unroll
        for (int e = 0; e < 8; e++) {
            unsigned long long ad = dup2(av[e]);
            #pragma unroll
            for (int p = 0; p < 4; p++) fma2(acc[e][p], ad, b[p]);
        }
    }

    // epilogue: add node projections + bias, activations, gated product, scatter
    const int d0 = tx * 4;
    float bfv[4], bsv[4];
    #pragma unroll
    for (int p = 0; p < 4; p++) { bfv[p] = bf[d0 + p]; bsv[p] = bs[d0 + p]; }

    #pragma unroll
    for (int e = 0; e < 8; e++) {
        int le = ty * 8 + e;
        int ge = e0 + le;
        if (ge >= n_edges) continue;
        int src = s_src[le];
        int tgt = s_tgt[le];
        const float4* p1 = (const float4*)(g_P1 + src * 128 + tx * 8);
        const float4* p2 = (const float4*)(g_P2 + tgt * 128 + tx * 8);
        float4 p1a = p1[0], p1b = p1[1];
        float4 p2a = p2[0], p2b = p2[1];
        float gp[4], vp[4];
        {
            float2 a0 = unpack2(acc[e][0]);
            float2 a1 = unpack2(acc[e][1]);
            float2 a2 = unpack2(acc[e][2]);
            float2 a3 = unpack2(acc[e][3]);
            gp[0] = a0.x + p1a.x + p2a.x + bfv[0];
            vp[0] = a0.y + p1a.y + p2a.y + bsv[0];
            gp[1] = a1.x + p1a.z + p2a.z + bfv[1];
            vp[1] = a1.y + p1a.w + p2a.w + bsv[1];
            gp[2] = a2.x + p1b.x + p2b.x + bfv[2];
            vp[2] = a2.y + p1b.y + p2b.y + bsv[2];
            gp[3] = a3.x + p1b.z + p2b.z + bfv[3];
            vp[3] = a3.y + p1b.w + p2b.w + bsv[3];
        }
        float m[4];
        #pragma unroll
        for (int p = 0; p < 4; p++) {
            float gate = 1.0f / (1.0f + expf(-gp[p]));
            float val  = softplus_f(vp[p]);
            m[p] = gate * val;
        }
        float* dst = &g_message[(long long)src * DCH + d0];
        asm volatile("red.global.add.v4.f32 [%0], {%1, %2, %3, %4};"
                     :: "l"(dst), "f"(m[0]), "f"(m[1]), "f"(m[2]), "f"(m[3])
                     : "memory");
    }
}

// ---------- pass 3: per-channel sum / sumsq ----------
__global__ void stats_kernel(int n_nodes) {
    int c = threadIdx.x & 63;
    int r = threadIdx.x >> 6;
    float s = 0.0f, q = 0.0f;
    for (int i = blockIdx.x * 4 + r; i < n_nodes; i += gridDim.x * 4) {
        float v = g_message[i * DCH + c];
        s += v;
        q += v * v;
    }
    __shared__ float sh_s[4][64];
    __shared__ float sh_q[4][64];
    sh_s[r][c] = s;
    sh_q[r][c] = q;
    __syncthreads();
    if (r == 0) {
        s = sh_s[0][c] + sh_s[1][c] + sh_s[2][c] + sh_s[3][c];
        q = sh_q[0][c] + sh_q[1][c] + sh_q[2][c] + sh_q[3][c];
        atomicAdd(&g_sum[c], s);
        atomicAdd(&g_sumsq[c], q);
    }
}

// ---------- pass 4: BN + residual + softplus ----------
__global__ void final_kernel(const float* __restrict__ x,
                             const float* __restrict__ gamma,
                             const float* __restrict__ beta,
                             float* __restrict__ out,
                             int total, float inv_n)
{
    int i = blockIdx.x * blockDim.x + threadIdx.x;
    if (i >= total) return;
    int c = i & 63;
    float mean = g_sum[c] * inv_n;
    float var  = g_sumsq[c] * inv_n - mean * mean;
    float inv_std = rsqrtf(var + 1e-5f);
    float mnorm = (g_message[i] - mean) * inv_std * gamma[c] + beta[c];
    float t = x[i] + mnorm;
    out[i] = softplus_f(t);
}

extern "C" void kernel_launch(void* const* d_in, const int* in_sizes, int n_in,
                              void* d_out, int out_size)
{
    const float* x     = (const float*)d_in[0];
    const float* ea    = (const float*)d_in[1];
    const float* Wf    = (const float*)d_in[2];
    const float* bf    = (const float*)d_in[3];
    const float* Ws    = (const float*)d_in[4];
    const float* bs    = (const float*)d_in[5];
    const float* gamma = (const float*)d_in[6];
    const float* beta  = (const float*)d_in[7];
    const int*   esrc  = (const int*)d_in[8];
    const int*   etgt  = (const int*)d_in[9];
    float* out = (float*)d_out;

    int n_nodes = in_sizes[0] / DCH;
    int n_edges = in_sizes[8];
    int total   = n_nodes * DCH;

    static bool attr_set = false;
    if (!attr_set) {
        cudaFuncSetAttribute(edge_kernel, cudaFuncAttributeMaxDynamicSharedMemorySize, EDGE_SMEM_BYTES);
        cudaFuncSetAttribute(node_proj_kernel, cudaFuncAttributeMaxDynamicSharedMemorySize, NODE_SMEM_BYTES);
        attr_set = true;
    }

    // pass 0: zero message scratch + stats
    {
        int grid = (total + 255) / 256;
        if (grid > 1024) grid = 1024;
        zero_kernel<<<grid, 256>>>(total);
    }
    // pass 1: node projections (independent of pass 0)
    {
        dim3 grid((n_nodes + 127) / 128, 2);
        node_proj_kernel<<<grid, 256, NODE_SMEM_BYTES>>>(x, Wf, Ws, n_nodes);
    }
    // pass 2: edge kernel
    {
        int grid = (n_edges + TILE_E - 1) / TILE_E;
        edge_kernel<<<grid, 256, EDGE_SMEM_BYTES>>>(ea, Wf, bf, Ws, bs, esrc, etgt, n_edges);
    }
    // pass 3: stats
    stats_kernel<<<148, 256>>>(n_nodes);
    // pass 4: BN + softplus
    {
        int grid = (total + 255) / 256;
        final_kernel<<<grid, 256>>>(x, gamma, beta, out, total, 1.0f / (float)n_nodes);
    }
}

// round 4
// speedup vs baseline: 4.8015x; 1.7520x over previous
#include <cuda_runtime.h>
#include <cuda_bf16.h>
#include <math.h>

#define DCH    64
#define FAN    192
#define TILE_E 128
#define KTOT   64
#define STRB   132
#define MAX_NODES 50176

__device__ float g_message[MAX_NODES * DCH];
__device__ float g_P1[MAX_NODES * 128];
__device__ float g_P2[MAX_NODES * 128];
__device__ float g_sum[DCH];
__device__ float g_sumsq[DCH];
__device__ unsigned short g_Bh[128 * 64];   // W3 interleaved [n][k] bf16 hi
__device__ unsigned short g_Bl[128 * 64];   // bf16 lo

// ---------------- node proj smem ----------------
#define SM_B_FLOATS   (KTOT * STRB)
#define SM_Z_FLOATS   (KTOT * 128)
#define NODE_SMEM_BYTES ((SM_B_FLOATS + SM_Z_FLOATS) * 4)   // 66560

// ---------------- edge kernel smem (bytes) ----------------
#define EO_SRC   0
#define EO_TGT   512
#define EO_AH    1024
#define EO_AL    (EO_AH + 16384)
#define EO_BH    (EO_AL + 16384)
#define EO_BL    (EO_BH + 16384)
#define EDGE_SMEM_BYTES (EO_BL + 16384)     // 66560
#define EO_STAGE 1024                        // reuses AH/AL(+BH head) after sync
#define STG 68                               // stage row stride in floats

// ---------------- helpers ----------------
__device__ __forceinline__ unsigned smem_u32(const void* p) {
    unsigned a;
    asm("{ .reg .u64 t; cvta.to.shared.u64 t, %1; cvt.u32.u64 %0, t; }" : "=r"(a) : "l"(p));
    return a;
}
__device__ __forceinline__ float ex2a(float x) { float r; asm("ex2.approx.f32 %0, %1;" : "=f"(r) : "f"(x)); return r; }
__device__ __forceinline__ float lg2a(float x) { float r; asm("lg2.approx.f32 %0, %1;" : "=f"(r) : "f"(x)); return r; }
__device__ __forceinline__ float rcpa(float x) { float r; asm("rcp.approx.f32 %0, %1;" : "=f"(r) : "f"(x)); return r; }
__device__ __forceinline__ float sigmoid_f(float g) {
    return rcpa(1.0f + ex2a(-1.44269504f * g));
}
__device__ __forceinline__ float softplus_f(float v) {
    float u = ex2a(-1.44269504f * fabsf(v));
    return fmaxf(v, 0.0f) + 0.69314718f * lg2a(1.0f + u);
}
// f32x2 for node proj
__device__ __forceinline__ void fma2(unsigned long long& c, unsigned long long a, unsigned long long b) {
    asm("fma.rn.f32x2 %0, %1, %2, %3;" : "=l"(c) : "l"(a), "l"(b), "l"(c));
}
__device__ __forceinline__ unsigned long long dup2(float a) {
    unsigned long long r;
    asm("mov.b64 %0, {%1, %1};" : "=l"(r) : "f"(a));
    return r;
}
__device__ __forceinline__ float2 unpack2(unsigned long long v) {
    float2 r;
    asm("mov.b64 {%0, %1}, %2;" : "=f"(r.x), "=f"(r.y) : "l"(v));
    return r;
}

#define LDSM4(R, A) \
    asm volatile("ldmatrix.sync.aligned.m8n8.x4.shared.b16 {%0,%1,%2,%3}, [%4];" \
        : "=r"((R)[0]), "=r"((R)[1]), "=r"((R)[2]), "=r"((R)[3]) : "r"(A))
#define LDSM2(R0, R1, A) \
    asm volatile("ldmatrix.sync.aligned.m8n8.x2.shared.b16 {%0,%1}, [%2];" \
        : "=r"(R0), "=r"(R1) : "r"(A))
#define MMA16816(D, A, B0, B1) \
    asm volatile("mma.sync.aligned.m16n8k16.row.col.f32.bf16.bf16.f32 " \
        "{%0,%1,%2,%3}, {%4,%5,%6,%7}, {%8,%9}, {%0,%1,%2,%3};" \
        : "+f"((D)[0]), "+f"((D)[1]), "+f"((D)[2]), "+f"((D)[3]) \
        : "r"((A)[0]), "r"((A)[1]), "r"((A)[2]), "r"((A)[3]), "r"(B0), "r"(B1))

// ---------------- prep: W3 -> bf16 hi/lo, [n][k] interleaved ----------------
__global__ void prep_B_kernel(const float* __restrict__ Wf, const float* __restrict__ Ws) {
    int idx = blockIdx.x * 256 + threadIdx.x;   // 8192
    int n = idx >> 6;
    int k = idx & 63;
    int d = n >> 1;
    const float* w = (n & 1) ? Ws : Wf;
    float v = w[d * FAN + 128 + k];
    __nv_bfloat16 h = __float2bfloat16_rn(v);
    float hf = __bfloat162float(h);
    __nv_bfloat16 l = __float2bfloat16_rn(v - hf);
    g_Bh[idx] = __bfloat16_as_ushort(h);
    g_Bl[idx] = __bfloat16_as_ushort(l);
}

// ---------------- zero kernels ----------------
__global__ void zero_kernel(int total4) {
    int i = blockIdx.x * blockDim.x + threadIdx.x;
    int stride = gridDim.x * blockDim.x;
    float4* m4 = (float4*)g_message;
    for (int j = i; j < total4; j += stride) m4[j] = make_float4(0.f, 0.f, 0.f, 0.f);
}
__global__ void zero_sums_kernel() {
    int i = threadIdx.x;
    if (i < DCH) { g_sum[i] = 0.0f; g_sumsq[i] = 0.0f; }
}

// ---------------- node projections (fp32 f32x2, proven) ----------------
__device__ __forceinline__ void fill_B_np(float* Bs, const float* __restrict__ Wf,
                                          const float* __restrict__ Ws, int kofs, int tid)
{
    #pragma unroll
    for (int j = 0; j < 32; j++) {
        int idx = tid + j * 256;
        int k = idx >> 7;
        int phys = idx & 127;
        int c  = phys >> 6;
        int r  = phys & 63;
        int tx = r >> 2;
        int j2 = r & 3;
        int d  = tx * 4 + c * 2 + (j2 >> 1);
        int gv = j2 & 1;
        const float* w = gv ? Ws : Wf;
        Bs[k * STRB + phys] = w[d * FAN + kofs + k];
    }
}

__global__ __launch_bounds__(256, 2)
void node_proj_kernel(const float* __restrict__ x,
                      const float* __restrict__ Wf,
                      const float* __restrict__ Ws,
                      int n_nodes, int wsel)
{
    extern __shared__ float sm[];
    float* Bs = sm;
    float* Zs = sm + SM_B_FLOATS;

    const int tid = threadIdx.x;
    const int tx = tid & 15;
    const int ty = tid >> 4;
    const int n0 = blockIdx.x * 128;
    float* P = wsel ? g_P2 : g_P1;

    fill_B_np(Bs, Wf, Ws, wsel * 64, tid);

    #pragma unroll
    for (int j = 0; j < 32; j++) {
        int idx = tid + j * 256;
        int k = idx & 63;
        int n = idx >> 6;
        float v = (n0 + n < n_nodes) ? x[(n0 + n) * DCH + k] : 0.0f;
        Zs[k * 128 + ((n + 4 * k) & 127)] = v;
    }
    __syncthreads();

    unsigned long long acc[8][4];
    #pragma unroll
    for (int e = 0; e < 8; e++)
        #pragma unroll
        for (int p = 0; p < 4; p++) acc[e][p] = 0ULL;

    #pragma unroll 4
    for (int k = 0; k < KTOT; k++) {
        const float* bro = Bs + k * STRB;
        ulonglong2 c0 = *(const ulonglong2*)(bro + tx * 4);
        ulonglong2 c1 = *(const ulonglong2*)(bro + 64 + tx * 4);
        unsigned long long b[4] = {c0.x, c0.y, c1.x, c1.y};
        int col0 = (ty * 8 + 4 * k) & 127;
        int col1 = (ty * 8 + 4 + 4 * k) & 127;
        float4 a03 = *(const float4*)(Zs + k * 128 + col0);
        float4 a47 = *(const float4*)(Zs + k * 128 + col1);
        float av[8] = {a03.x, a03.y, a03.z, a03.w, a47.x, a47.y, a47.z, a47.w};
        #pragma unroll
        for (int e = 0; e < 8; e++) {
            unsigned long long ad = dup2(av[e]);
            #pragma unroll
            for (int p = 0; p < 4; p++) fma2(acc[e][p], ad, b[p]);
        }
    }

    #pragma unroll
    for (int e = 0; e < 8; e++) {
        int n = n0 + ty * 8 + e;
        if (n >= n_nodes) continue;
        float2 v0 = unpack2(acc[e][0]);
        float2 v1 = unpack2(acc[e][1]);
        float2 v2 = unpack2(acc[e][2]);
        float2 v3 = unpack2(acc[e][3]);
        float4* dst = (float4*)(P + n * 128 + tx * 8);
        dst[0] = make_float4(v0.x, v0.y, v1.x, v1.y);
        dst[1] = make_float4(v2.x, v2.y, v3.x, v3.y);
    }
}

// ---------------- edge kernel: mma.sync bf16 hi/lo + epilogue ----------------
__global__ __launch_bounds__(256, 2)
void edge_mma_kernel(const float* __restrict__ ea,
                     const float* __restrict__ bfb,
                     const float* __restrict__ bsb,
                     const int*   __restrict__ esrc,
                     const int*   __restrict__ etgt,
                     int n_edges)
{
    extern __shared__ char smc[];
    unsigned sb = smem_u32(smc);
    int* s_src = (int*)(smc + EO_SRC);
    int* s_tgt = (int*)(smc + EO_TGT);
    const int tid = threadIdx.x;
    const int e0 = blockIdx.x * TILE_E;

    // ---- fill B tiles (swizzled) from pre-prepped gmem ----
    {
        const uint4* bh = (const uint4*)g_Bh;
        const uint4* bl = (const uint4*)g_Bl;
        #pragma unroll
        for (int j = 0; j < 4; j++) {
            int idx = tid + j * 256;        // 1024 chunks of 16B
            int n = idx >> 3;
            int cj = idx & 7;
            unsigned dst = n * 128 + ((cj * 16) ^ ((n & 7) << 4));
            *(uint4*)(smc + EO_BH + dst) = bh[idx];
            *(uint4*)(smc + EO_BL + dst) = bl[idx];
        }
    }
    // ---- fill A tiles: ea -> bf16 hi/lo, swizzled ----
    #pragma unroll
    for (int j = 0; j < 4; j++) {
        int idx = tid + j * 256;            // 1024 chunks (e, k-group of 8)
        int e = idx >> 3;
        int cj = idx & 7;
        int ge = e0 + e;
        float4 v0, v1;
        if (ge < n_edges) {
            const float4* src = (const float4*)ea + (size_t)ge * 16 + cj * 2;
            v0 = src[0]; v1 = src[1];
        } else {
            v0 = make_float4(0.f, 0.f, 0.f, 0.f);
            v1 = v0;
        }
        float vv[8] = {v0.x, v0.y, v0.z, v0.w, v1.x, v1.y, v1.z, v1.w};
        unsigned H[4], L[4];
        #pragma unroll
        for (int p = 0; p < 4; p++) {
            __nv_bfloat16 h0 = __float2bfloat16_rn(vv[2 * p]);
            __nv_bfloat16 h1 = __float2bfloat16_rn(vv[2 * p + 1]);
            float f0 = __bfloat162float(h0), f1 = __bfloat162float(h1);
            __nv_bfloat16 l0 = __float2bfloat16_rn(vv[2 * p] - f0);
            __nv_bfloat16 l1 = __float2bfloat16_rn(vv[2 * p + 1] - f1);
            H[p] = (unsigned)__bfloat16_as_ushort(h0) | ((unsigned)__bfloat16_as_ushort(h1) << 16);
            L[p] = (unsigned)__bfloat16_as_ushort(l0) | ((unsigned)__bfloat16_as_ushort(l1) << 16);
        }
        unsigned dst = e * 128 + ((cj * 16) ^ ((e & 7) << 4));
        *(uint4*)(smc + EO_AH + dst) = make_uint4(H[0], H[1], H[2], H[3]);
        *(uint4*)(smc + EO_AL + dst) = make_uint4(L[0], L[1], L[2], L[3]);
    }
    if (tid < TILE_E) {
        int ge = e0 + tid;
        s_src[tid] = (ge < n_edges) ? esrc[ge] : 0;
        s_tgt[tid] = (ge < n_edges) ? etgt[ge] : 0;
    }
    __syncthreads();

    // ---- mma mainloop ----
    const int w = tid >> 5;
    const int lane = tid & 31;
    const int m0 = (w & 3) * 32;
    const int nn0 = (w >> 2) * 64;

    float acc[2][8][4];
    #pragma unroll
    for (int mt = 0; mt < 2; mt++)
        #pragma unroll
        for (int nt = 0; nt < 8; nt++)
            #pragma unroll
            for (int p = 0; p < 4; p++) acc[mt][nt][p] = 0.0f;

    const int rA0 = m0 + (lane & 15);
    const unsigned hiA = ((lane >> 4) & 1) << 4;
    const unsigned swA = (rA0 & 7) << 4;     // same for rA0 and rA0+16
    const unsigned aoff0 = sb + EO_AH + rA0 * 128;
    const unsigned aoff1 = aoff0 + 16 * 128;
    const int rB = nn0 + (lane & 7);
    const unsigned hiB = ((lane >> 3) & 1) << 4;
    const unsigned swB = (lane & 7) << 4;
    const unsigned boff = sb + EO_BH + rB * 128;

    #pragma unroll
    for (int kc = 0; kc < 4; kc++) {
        unsigned ka = (unsigned)(kc * 32 + hiA) ^ swA;
        unsigned ah[4], ah2[4], al[4], al2[4];
        LDSM4(ah,  aoff0 + ka);
        LDSM4(ah2, aoff1 + ka);
        LDSM4(al,  aoff0 + ka + 16384);
        LDSM4(al2, aoff1 + ka + 16384);
        unsigned kb = (unsigned)(kc * 32 + hiB) ^ swB;
        #pragma unroll
        for (int nt = 0; nt < 8; nt++) {
            unsigned ba = boff + nt * 8 * 128 + kb;
            unsigned bh0, bh1, bl0, bl1;
            LDSM2(bh0, bh1, ba);
            LDSM2(bl0, bl1, ba + 16384);
            MMA16816(acc[0][nt], ah,  bh0, bh1);
            MMA16816(acc[1][nt], ah2, bh0, bh1);
            MMA16816(acc[0][nt], ah,  bl0, bl1);
            MMA16816(acc[1][nt], ah2, bl0, bl1);
            MMA16816(acc[0][nt], al,  bh0, bh1);
            MMA16816(acc[1][nt], al2, bh0, bh1);
        }
    }

    __syncthreads();   // all ldmatrix done; safe to reuse A/B smem as stage

    // ---- epilogue: add node projections + bias, activate, stage ----
    float* stage = (float*)(smc + EO_STAGE);
    const int cq = lane & 3;
    const int cbase = (w >> 2) * 32;
    float bfv[8], bsv[8];
    #pragma unroll
    for (int nt = 0; nt < 8; nt++) {
        int c = cbase + nt * 4 + cq;
        bfv[nt] = bfb[c];
        bsv[nt] = bsb[c];
    }

    #pragma unroll
    for (int mt = 0; mt < 2; mt++) {
        int elo = m0 + mt * 16 + (lane >> 2);
        int ehi = elo + 8;
        const float* P1l = g_P1 + (size_t)s_src[elo] * 128;
        const float* P2l = g_P2 + (size_t)s_tgt[elo] * 128;
        const float* P1h = g_P1 + (size_t)s_src[ehi] * 128;
        const float* P2h = g_P2 + (size_t)s_tgt[ehi] * 128;
        #pragma unroll
        for (int nt = 0; nt < 8; nt++) {
            int c = cbase + nt * 4 + cq;
            float2 q1l = *(const float2*)(P1l + 2 * c);
            float2 q2l = *(const float2*)(P2l + 2 * c);
            float2 q1h = *(const float2*)(P1h + 2 * c);
            float2 q2h = *(const float2*)(P2h + 2 * c);
            float glo = acc[mt][nt][0] + q1l.x + q2l.x + bfv[nt];
            float vlo = acc[mt][nt][1] + q1l.y + q2l.y + bsv[nt];
            float ghi = acc[mt][nt][2] + q1h.x + q2h.x + bfv[nt];
            float vhi = acc[mt][nt][3] + q1h.y + q2h.y + bsv[nt];
            stage[elo * STG + c] = sigmoid_f(glo) * softplus_f(vlo);
            stage[ehi * STG + c] = sigmoid_f(ghi) * softplus_f(vhi);
        }
    }
    __syncthreads();

    // ---- scatter: 2 threads per edge, red.v4 x8 each ----
    {
        int e = tid >> 1;
        int half = tid & 1;
        int ge = e0 + e;
        if (ge < n_edges) {
            float* dst = g_message + (size_t)s_src[e] * 64 + half * 32;
            const float* srow = stage + e * STG + half * 32;
            #pragma unroll
            for (int q = 0; q < 8; q++) {
                float4 v = *(const float4*)(srow + q * 4);
                asm volatile("red.global.add.v4.f32 [%0], {%1, %2, %3, %4};"
                             :: "l"(dst + q * 4), "f"(v.x), "f"(v.y), "f"(v.z), "f"(v.w)
                             : "memory");
            }
        }
    }
}

// ---------------- stats ----------------
__global__ __launch_bounds__(256)
void stats_kernel(int n4) {
    int t = blockIdx.x * blockDim.x + threadIdx.x;
    int stride = gridDim.x * blockDim.x;
    const float4* m4 = (const float4*)g_message;
    float4 s = make_float4(0.f, 0.f, 0.f, 0.f);
    float4 q = make_float4(0.f, 0.f, 0.f, 0.f);
    for (int i = t; i < n4; i += stride) {
        float4 v = m4[i];
        s.x += v.x; s.y += v.y; s.z += v.z; s.w += v.w;
        q.x += v.x * v.x; q.y += v.y * v.y; q.z += v.z * v.z; q.w += v.w * v.w;
    }
    __shared__ float4 ss[256];
    __shared__ float4 qq[256];
    ss[threadIdx.x] = s;
    qq[threadIdx.x] = q;
    __syncthreads();
    #pragma unroll
    for (int off = 128; off >= 16; off >>= 1) {
        if (threadIdx.x < off) {
            float4 a = ss[threadIdx.x + off], b = qq[threadIdx.x + off];
            float4 sa = ss[threadIdx.x], qa = qq[threadIdx.x];
            sa.x += a.x; sa.y += a.y; sa.z += a.z; sa.w += a.w;
            qa.x += b.x; qa.y += b.y; qa.z += b.z; qa.w += b.w;
            ss[threadIdx.x] = sa;
            qq[threadIdx.x] = qa;
        }
        __syncthreads();
    }
    if (threadIdx.x < 16) {
        int c = threadIdx.x * 4;
        float4 sa = ss[threadIdx.x], qa = qq[threadIdx.x];
        atomicAdd(&g_sum[c + 0], sa.x); atomicAdd(&g_sum[c + 1], sa.y);
        atomicAdd(&g_sum[c + 2], sa.z); atomicAdd(&g_sum[c + 3], sa.w);
        atomicAdd(&g_sumsq[c + 0], qa.x); atomicAdd(&g_sumsq[c + 1], qa.y);
        atomicAdd(&g_sumsq[c + 2], qa.z); atomicAdd(&g_sumsq[c + 3], qa.w);
    }
}

// ---------------- final: BN + residual + softplus ----------------
__global__ __launch_bounds__(256)
void final_kernel(const float* __restrict__ x,
                  const float* __restrict__ gamma,
                  const float* __restrict__ beta,
                  float* __restrict__ out,
                  int n4, float inv_n)
{
    int i = blockIdx.x * blockDim.x + threadIdx.x;
    if (i >= n4) return;
    int c = (i & 15) * 4;
    float4 mm = ((const float4*)g_message)[i];
    float4 xx = ((const float4*)x)[i];
    float4 gm = ((const float4*)gamma)[i & 15];
    float4 bt = ((const float4*)beta)[i & 15];
    float mv[4] = {mm.x, mm.y, mm.z, mm.w};
    float xv[4] = {xx.x, xx.y, xx.z, xx.w};
    float gv[4] = {gm.x, gm.y, gm.z, gm.w};
    float bv[4] = {bt.x, bt.y, bt.z, bt.w};
    float ov[4];
    #pragma unroll
    for (int j = 0; j < 4; j++) {
        float mean = g_sum[c + j] * inv_n;
        float var  = g_sumsq[c + j] * inv_n - mean * mean;
        float inv_std = rsqrtf(var + 1e-5f);
        float mn = (mv[j] - mean) * inv_std * gv[j] + bv[j];
        float t = xv[j] + mn;
        ov[j] = fmaxf(t, 0.0f) + log1pf(expf(-fabsf(t)));
    }
    ((float4*)out)[i] = make_float4(ov[0], ov[1], ov[2], ov[3]);
}

extern "C" void kernel_launch(void* const* d_in, const int* in_sizes, int n_in,
                              void* d_out, int out_size)
{
    const float* x     = (const float*)d_in[0];
    const float* ea    = (const float*)d_in[1];
    const float* Wf    = (const float*)d_in[2];
    const float* bf    = (const float*)d_in[3];
    const float* Ws    = (const float*)d_in[4];
    const float* bs    = (const float*)d_in[5];
    const float* gamma = (const float*)d_in[6];
    const float* beta  = (const float*)d_in[7];
    const int*   esrc  = (const int*)d_in[8];
    const int*   etgt  = (const int*)d_in[9];
    float* out = (float*)d_out;

    int n_nodes = in_sizes[0] / DCH;
    int n_edges = in_sizes[8];
    int total   = n_nodes * DCH;
    int total4  = total / 4;

    static bool attr_set = false;
    if (!attr_set) {
        cudaFuncSetAttribute(edge_mma_kernel, cudaFuncAttributeMaxDynamicSharedMemorySize, EDGE_SMEM_BYTES);
        cudaFuncSetAttribute(node_proj_kernel, cudaFuncAttributeMaxDynamicSharedMemorySize, NODE_SMEM_BYTES);
        attr_set = true;
    }

    prep_B_kernel<<<32, 256>>>(Wf, Ws);                                      // 1
    {
        int grid = (total4 + 255) / 256;
        if (grid > 1024) grid = 1024;
        zero_kernel<<<grid, 256>>>(total4);                                  // 2
    }
    {
        int grid = (n_nodes + 127) / 128;
        node_proj_kernel<<<grid, 256, NODE_SMEM_BYTES>>>(x, Wf, Ws, n_nodes, 0);  // 3
        node_proj_kernel<<<grid, 256, NODE_SMEM_BYTES>>>(x, Wf, Ws, n_nodes, 1);  // 4
    }
    zero_sums_kernel<<<1, 64>>>();                                           // 5
    {
        int grid = (n_edges + TILE_E - 1) / TILE_E;
        edge_mma_kernel<<<grid, 256, EDGE_SMEM_BYTES>>>(ea, bf, bs, esrc, etgt, n_edges);  // 6
    }
    stats_kernel<<<512, 256>>>(total4);                                      // 7
    {
        int grid = (total4 + 255) / 256;
        final_kernel<<<grid, 256>>>(x, gamma, beta, out, total4, 1.0f / (float)n_nodes);   // 8
    }
}

// round 6
// speedup vs baseline: 5.0655x; 1.0550x over previous
#include <cuda_runtime.h>
#include <cuda_fp16.h>
#include <math.h>

#define DCH    64
#define FAN    192
#define TILE_E 128
#define KTOT   64
#define STRB   132
#define MAX_NODES 50176

__device__ float g_message[MAX_NODES * DCH];
__device__ float g_P1[MAX_NODES * 128];
__device__ float g_P2[MAX_NODES * 128];
__device__ float g_sum[DCH];
__device__ float g_sumsq[DCH];
__device__ unsigned short g_Bh[128 * 64];   // W3 interleaved [n][k] fp16 hi
__device__ unsigned short g_Bl[128 * 64];   // fp16 lo

// ---------------- node proj smem ----------------
#define SM_B_FLOATS   (KTOT * STRB)
#define SM_Z_FLOATS   (KTOT * 128)
#define NODE_SMEM_BYTES ((SM_B_FLOATS + SM_Z_FLOATS) * 4)   // 66560

// ---------------- edge kernel smem (bytes) ----------------
#define EO_SRC   0
#define EO_TGT   512
#define EO_AH    1024
#define EO_BH    (EO_AH + 16384)            // 17408
#define EO_BL    (EO_BH + 16384)            // 33792
#define EDGE_SMEM_BYTES (EO_BL + 16384)     // 50176
#define EO_STAGE 1024                        // reuses AH/BH/BL after final LDSM
#define STG 68

// ---------------- helpers ----------------
__device__ __forceinline__ unsigned smem_u32(const void* p) {
    unsigned a;
    asm("{ .reg .u64 t; cvta.to.shared.u64 t, %1; cvt.u32.u64 %0, t; }" : "=r"(a) : "l"(p));
    return a;
}
__device__ __forceinline__ unsigned pack_f16x2(float lo, float hi) {
    unsigned r;
    asm("cvt.rn.f16x2.f32 %0, %1, %2;" : "=r"(r) : "f"(hi), "f"(lo));
    return r;
}
__device__ __forceinline__ float ex2a(float x) { float r; asm("ex2.approx.f32 %0, %1;" : "=f"(r) : "f"(x)); return r; }
__device__ __forceinline__ float lg2a(float x) { float r; asm("lg2.approx.f32 %0, %1;" : "=f"(r) : "f"(x)); return r; }
__device__ __forceinline__ float rcpa(float x) { float r; asm("rcp.approx.f32 %0, %1;" : "=f"(r) : "f"(x)); return r; }
__device__ __forceinline__ float sigmoid_f(float g) {
    return rcpa(1.0f + ex2a(-1.44269504f * g));
}
__device__ __forceinline__ float softplus_f(float v) {
    float u = ex2a(-1.44269504f * fabsf(v));
    return fmaxf(v, 0.0f) + 0.69314718f * lg2a(1.0f + u);
}
__device__ __forceinline__ void fma2(unsigned long long& c, unsigned long long a, unsigned long long b) {
    asm("fma.rn.f32x2 %0, %1, %2, %3;" : "=l"(c) : "l"(a), "l"(b), "l"(c));
}
__device__ __forceinline__ unsigned long long dup2(float a) {
    unsigned long long r;
    asm("mov.b64 %0, {%1, %1};" : "=l"(r) : "f"(a));
    return r;
}
__device__ __forceinline__ float2 unpack2(unsigned long long v) {
    float2 r;
    asm("mov.b64 {%0, %1}, %2;" : "=f"(r.x), "=f"(r.y) : "l"(v));
    return r;
}

#define LDSM4(R, A) \
    asm volatile("ldmatrix.sync.aligned.m8n8.x4.shared.b16 {%0,%1,%2,%3}, [%4];" \
        : "=r"((R)[0]), "=r"((R)[1]), "=r"((R)[2]), "=r"((R)[3]) : "r"(A))
#define LDSM2(R0, R1, A) \
    asm volatile("ldmatrix.sync.aligned.m8n8.x2.shared.b16 {%0,%1}, [%2];" \
        : "=r"(R0), "=r"(R1) : "r"(A))
#define MMA16816(D, A, B0, B1) \
    asm volatile("mma.sync.aligned.m16n8k16.row.col.f32.f16.f16.f32 " \
        "{%0,%1,%2,%3}, {%4,%5,%6,%7}, {%8,%9}, {%0,%1,%2,%3};" \
        : "+f"((D)[0]), "+f"((D)[1]), "+f"((D)[2]), "+f"((D)[3]) \
        : "r"((A)[0]), "r"((A)[1]), "r"((A)[2]), "r"((A)[3]), "r"(B0), "r"(B1))

// ---------------- prep: W3 -> fp16 hi/lo, [n][k] interleaved ----------------
__global__ void prep_B_kernel(const float* __restrict__ Wf, const float* __restrict__ Ws) {
    int idx = blockIdx.x * 256 + threadIdx.x;   // 8192
    int n = idx >> 6;
    int k = idx & 63;
    int d = n >> 1;
    const float* w = (n & 1) ? Ws : Wf;
    float v = w[d * FAN + 128 + k];
    __half h = __float2half_rn(v);
    float hf = __half2float(h);
    __half l = __float2half_rn(v - hf);
    g_Bh[idx] = __half_as_ushort(h);
    g_Bl[idx] = __half_as_ushort(l);
}

// ---------------- zero ----------------
__global__ void zero_kernel(int total4) {
    int i = blockIdx.x * blockDim.x + threadIdx.x;
    int stride = gridDim.x * blockDim.x;
    float4* m4 = (float4*)g_message;
    for (int j = i; j < total4; j += stride) m4[j] = make_float4(0.f, 0.f, 0.f, 0.f);
    if (i < DCH) { g_sum[i] = 0.0f; g_sumsq[i] = 0.0f; }
}

// ---------------- node projections (fp32 f32x2) ----------------
__device__ __forceinline__ void fill_B_np(float* Bs, const float* __restrict__ Wf,
                                          const float* __restrict__ Ws, int kofs, int tid)
{
    #pragma unroll
    for (int j = 0; j < 32; j++) {
        int idx = tid + j * 256;
        int k = idx >> 7;
        int phys = idx & 127;
        int c  = phys >> 6;
        int r  = phys & 63;
        int tx = r >> 2;
        int j2 = r & 3;
        int d  = tx * 4 + c * 2 + (j2 >> 1);
        int gv = j2 & 1;
        const float* w = gv ? Ws : Wf;
        Bs[k * STRB + phys] = w[d * FAN + kofs + k];
    }
}

__global__ __launch_bounds__(256, 2)
void node_proj_kernel(const float* __restrict__ x,
                      const float* __restrict__ Wf,
                      const float* __restrict__ Ws,
                      int n_nodes)
{
    extern __shared__ float sm[];
    float* Bs = sm;
    float* Zs = sm + SM_B_FLOATS;

    const int tid = threadIdx.x;
    const int tx = tid & 15;
    const int ty = tid >> 4;
    const int n0 = blockIdx.x * 128;
    const int wsel = blockIdx.y;
    float* P = wsel ? g_P2 : g_P1;

    fill_B_np(Bs, Wf, Ws, wsel * 64, tid);

    #pragma unroll
    for (int j = 0; j < 32; j++) {
        int idx = tid + j * 256;
        int k = idx & 63;
        int n = idx >> 6;
        float v = (n0 + n < n_nodes) ? x[(n0 + n) * DCH + k] : 0.0f;
        Zs[k * 128 + ((n + 4 * k) & 127)] = v;
    }
    __syncthreads();

    unsigned long long acc[8][4];
    #pragma unroll
    for (int e = 0; e < 8; e++)
        #pragma unroll
        for (int p = 0; p < 4; p++) acc[e][p] = 0ULL;

    #pragma unroll 4
    for (int k = 0; k < KTOT; k++) {
        const float* bro = Bs + k * STRB;
        ulonglong2 c0 = *(const ulonglong2*)(bro + tx * 4);
        ulonglong2 c1 = *(const ulonglong2*)(bro + 64 + tx * 4);
        unsigned long long b[4] = {c0.x, c0.y, c1.x, c1.y};
        int col0 = (ty * 8 + 4 * k) & 127;
        int col1 = (ty * 8 + 4 + 4 * k) & 127;
        float4 a03 = *(const float4*)(Zs + k * 128 + col0);
        float4 a47 = *(const float4*)(Zs + k * 128 + col1);
        float av[8] = {a03.x, a03.y, a03.z, a03.w, a47.x, a47.y, a47.z, a47.w};
        #pragma unroll
        for (int e = 0; e < 8; e++) {
            unsigned long long ad = dup2(av[e]);
            #pragma unroll
            for (int p = 0; p < 4; p++) fma2(acc[e][p], ad, b[p]);
        }
    }

    #pragma unroll
    for (int e = 0; e < 8; e++) {
        int n = n0 + ty * 8 + e;
        if (n >= n_nodes) continue;
        float2 v0 = unpack2(acc[e][0]);
        float2 v1 = unpack2(acc[e][1]);
        float2 v2 = unpack2(acc[e][2]);
        float2 v3 = unpack2(acc[e][3]);
        float4* dst = (float4*)(P + n * 128 + tx * 8);
        dst[0] = make_float4(v0.x, v0.y, v1.x, v1.y);
        dst[1] = make_float4(v2.x, v2.y, v3.x, v3.y);
    }
}

// ---------------- edge kernel: mma.sync fp16 2-term + epilogue ----------------
__global__ __launch_bounds__(256, 2)
void edge_mma_kernel(const float* __restrict__ ea,
                     const float* __restrict__ bfb,
                     const float* __restrict__ bsb,
                     const int*   __restrict__ esrc,
                     const int*   __restrict__ etgt,
                     int n_edges)
{
    extern __shared__ char smc[];
    unsigned sb = smem_u32(smc);
    int* s_src = (int*)(smc + EO_SRC);
    int* s_tgt = (int*)(smc + EO_TGT);
    const int tid = threadIdx.x;
    const int e0 = blockIdx.x * TILE_E;

    // ---- fill B tiles (swizzled) ----
    {
        const uint4* bh = (const uint4*)g_Bh;
        const uint4* bl = (const uint4*)g_Bl;
        #pragma unroll
        for (int j = 0; j < 4; j++) {
            int idx = tid + j * 256;
            int n = idx >> 3;
            int cj = idx & 7;
            unsigned dst = n * 128 + ((cj * 16) ^ ((n & 7) << 4));
            *(uint4*)(smc + EO_BH + dst) = bh[idx];
            *(uint4*)(smc + EO_BL + dst) = bl[idx];
        }
    }
    // ---- fill A tile: ea -> fp16 hi, swizzled ----
    #pragma unroll
    for (int j = 0; j < 4; j++) {
        int idx = tid + j * 256;
        int e = idx >> 3;
        int cj = idx & 7;
        int ge = e0 + e;
        float4 v0, v1;
        if (ge < n_edges) {
            const float4* src = (const float4*)ea + (size_t)ge * 16 + cj * 2;
            v0 = src[0]; v1 = src[1];
        } else {
            v0 = make_float4(0.f, 0.f, 0.f, 0.f);
            v1 = v0;
        }
        unsigned H[4];
        H[0] = pack_f16x2(v0.x, v0.y);
        H[1] = pack_f16x2(v0.z, v0.w);
        H[2] = pack_f16x2(v1.x, v1.y);
        H[3] = pack_f16x2(v1.z, v1.w);
        unsigned dst = e * 128 + ((cj * 16) ^ ((e & 7) << 4));
        *(uint4*)(smc + EO_AH + dst) = make_uint4(H[0], H[1], H[2], H[3]);
    }
    if (tid < TILE_E) {
        int ge = e0 + tid;
        s_src[tid] = (ge < n_edges) ? esrc[ge] : 0;
        s_tgt[tid] = (ge < n_edges) ? etgt[ge] : 0;
    }
    __syncthreads();

    // ---- mma mainloop ----
    const int w = tid >> 5;
    const int lane = tid & 31;
    const int m0 = (w & 3) * 32;
    const int nn0 = (w >> 2) * 64;

    float acc[2][8][4];
    #pragma unroll
    for (int mt = 0; mt < 2; mt++)
        #pragma unroll
        for (int nt = 0; nt < 8; nt++)
            #pragma unroll
            for (int p = 0; p < 4; p++) acc[mt][nt][p] = 0.0f;

    const int rA0 = m0 + (lane & 15);
    const unsigned hiA = ((lane >> 4) & 1) << 4;
    const unsigned swA = (rA0 & 7) << 4;
    const unsigned aoff0 = sb + EO_AH + rA0 * 128;
    const unsigned aoff1 = aoff0 + 16 * 128;
    const int rB = nn0 + (lane & 7);
    const unsigned hiB = ((lane >> 3) & 1) << 4;
    const unsigned swB = (lane & 7) << 4;
    const unsigned boff = sb + EO_BH + rB * 128;

    #pragma unroll
    for (int kc = 0; kc < 4; kc++) {
        unsigned ka = (unsigned)(kc * 32 + hiA) ^ swA;
        unsigned ah[4], ah2[4];
        LDSM4(ah,  aoff0 + ka);
        LDSM4(ah2, aoff1 + ka);
        unsigned kb = (unsigned)(kc * 32 + hiB) ^ swB;
        #pragma unroll
        for (int nt = 0; nt < 8; nt++) {
            unsigned ba = boff + nt * 8 * 128 + kb;
            unsigned bh0, bh1, bl0, bl1;
            LDSM2(bh0, bh1, ba);
            LDSM2(bl0, bl1, ba + 16384);
            MMA16816(acc[0][nt], ah,  bh0, bh1);
            MMA16816(acc[1][nt], ah2, bh0, bh1);
            MMA16816(acc[0][nt], ah,  bl0, bl1);
            MMA16816(acc[1][nt], ah2, bl0, bl1);
        }
    }

    __syncthreads();

    // ---- epilogue: node proj + bias, activate, stage ----
    float* stage = (float*)(smc + EO_STAGE);
    const int cq = lane & 3;
    const int cbase = (w >> 2) * 32;
    float bfv[8], bsv[8];
    #pragma unroll
    for (int nt = 0; nt < 8; nt++) {
        int c = cbase + nt * 4 + cq;
        bfv[nt] = bfb[c];
        bsv[nt] = bsb[c];
    }

    #pragma unroll
    for (int mt = 0; mt < 2; mt++) {
        int elo = m0 + mt * 16 + (lane >> 2);
        int ehi = elo + 8;
        const float* P1l = g_P1 + (size_t)s_src[elo] * 128;
        const float* P2l = g_P2 + (size_t)s_tgt[elo] * 128;
        const float* P1h = g_P1 + (size_t)s_src[ehi] * 128;
        const float* P2h = g_P2 + (size_t)s_tgt[ehi] * 128;
        #pragma unroll
        for (int nt = 0; nt < 8; nt++) {
            int c = cbase + nt * 4 + cq;
            float2 q1l = *(const float2*)(P1l + 2 * c);
            float2 q2l = *(const float2*)(P2l + 2 * c);
            float2 q1h = *(const float2*)(P1h + 2 * c);
            float2 q2h = *(const float2*)(P2h + 2 * c);
            float glo = acc[mt][nt][0] + q1l.x + q2l.x + bfv[nt];
            float vlo = acc[mt][nt][1] + q1l.y + q2l.y + bsv[nt];
            float ghi = acc[mt][nt][2] + q1h.x + q2h.x + bfv[nt];
            float vhi = acc[mt][nt][3] + q1h.y + q2h.y + bsv[nt];
            stage[elo * STG + c] = sigmoid_f(glo) * softplus_f(vlo);
            stage[ehi * STG + c] = sigmoid_f(ghi) * softplus_f(vhi);
        }
    }
    __syncthreads();

    // ---- scatter ----
    {
        int e = tid >> 1;
        int half = tid & 1;
        int ge = e0 + e;
        if (ge < n_edges) {
            float* dst = g_message + (size_t)s_src[e] * 64 + half * 32;
            const float* srow = stage + e * STG + half * 32;
            #pragma unroll
            for (int q = 0; q < 8; q++) {
                float4 v = *(const float4*)(srow + q * 4);
                asm volatile("red.global.add.v4.f32 [%0], {%1, %2, %3, %4};"
                             :: "l"(dst + q * 4), "f"(v.x), "f"(v.y), "f"(v.z), "f"(v.w)
                             : "memory");
            }
        }
    }
}

// ---------------- stats ----------------
__global__ __launch_bounds__(256)
void stats_kernel(int n4) {
    int t = blockIdx.x * blockDim.x + threadIdx.x;
    int stride = gridDim.x * blockDim.x;
    const float4* m4 = (const float4*)g_message;
    float4 s = make_float4(0.f, 0.f, 0.f, 0.f);
    float4 q = make_float4(0.f, 0.f, 0.f, 0.f);
    for (int i = t; i < n4; i += stride) {
        float4 v = m4[i];
        s.x += v.x; s.y += v.y; s.z += v.z; s.w += v.w;
        q.x += v.x * v.x; q.y += v.y * v.y; q.z += v.z * v.z; q.w += v.w * v.w;
    }
    __shared__ float4 ss[256];
    __shared__ float4 qq[256];
    ss[threadIdx.x] = s;
    qq[threadIdx.x] = q;
    __syncthreads();
    #pragma unroll
    for (int off = 128; off >= 16; off >>= 1) {
        if (threadIdx.x < off) {
            float4 a = ss[threadIdx.x + off], b = qq[threadIdx.x + off];
            float4 sa = ss[threadIdx.x], qa = qq[threadIdx.x];
            sa.x += a.x; sa.y += a.y; sa.z += a.z; sa.w += a.w;
            qa.x += b.x; qa.y += b.y; qa.z += b.z; qa.w += b.w;
            ss[threadIdx.x] = sa;
            qq[threadIdx.x] = qa;
        }
        __syncthreads();
    }
    if (threadIdx.x < 16) {
        int c = threadIdx.x * 4;
        float4 sa = ss[threadIdx.x], qa = qq[threadIdx.x];
        atomicAdd(&g_sum[c + 0], sa.x); atomicAdd(&g_sum[c + 1], sa.y);
        atomicAdd(&g_sum[c + 2], sa.z); atomicAdd(&g_sum[c + 3], sa.w);
        atomicAdd(&g_sumsq[c + 0], qa.x); atomicAdd(&g_sumsq[c + 1], qa.y);
        atomicAdd(&g_sumsq[c + 2], qa.z); atomicAdd(&g_sumsq[c + 3], qa.w);
    }
}

// ---------------- final ----------------
__global__ __launch_bounds__(256)
void final_kernel(const float* __restrict__ x,
                  const float* __restrict__ gamma,
                  const float* __restrict__ beta,
                  float* __restrict__ out,
                  int n4, float inv_n)
{
    int i = blockIdx.x * blockDim.x + threadIdx.x;
    if (i >= n4) return;
    int c = (i & 15) * 4;
    float4 mm = ((const float4*)g_message)[i];
    float4 xx = ((const float4*)x)[i];
    float4 gm = ((const float4*)gamma)[i & 15];
    float4 bt = ((const float4*)beta)[i & 15];
    float mv[4] = {mm.x, mm.y, mm.z, mm.w};
    float xv[4] = {xx.x, xx.y, xx.z, xx.w};
    float gv[4] = {gm.x, gm.y, gm.z, gm.w};
    float bv[4] = {bt.x, bt.y, bt.z, bt.w};
    float ov[4];
    #pragma unroll
    for (int j = 0; j < 4; j++) {
        float mean = g_sum[c + j] * inv_n;
        float var  = g_sumsq[c + j] * inv_n - mean * mean;
        float inv_std = rsqrtf(var + 1e-5f);
        float mn = (mv[j] - mean) * inv_std * gv[j] + bv[j];
        float t = xv[j] + mn;
        ov[j] = fmaxf(t, 0.0f) + log1pf(expf(-fabsf(t)));
    }
    ((float4*)out)[i] = make_float4(ov[0], ov[1], ov[2], ov[3]);
}

extern "C" void kernel_launch(void* const* d_in, const int* in_sizes, int n_in,
                              void* d_out, int out_size)
{
    const float* x     = (const float*)d_in[0];
    const float* ea    = (const float*)d_in[1];
    const float* Wf    = (const float*)d_in[2];
    const float* bf    = (const float*)d_in[3];
    const float* Ws    = (const float*)d_in[4];
    const float* bs    = (const float*)d_in[5];
    const float* gamma = (const float*)d_in[6];
    const float* beta  = (const float*)d_in[7];
    const int*   esrc  = (const int*)d_in[8];
    const int*   etgt  = (const int*)d_in[9];
    float* out = (float*)d_out;

    int n_nodes = in_sizes[0] / DCH;
    int n_edges = in_sizes[8];
    int total   = n_nodes * DCH;
    int total4  = total / 4;

    static bool attr_set = false;
    if (!attr_set) {
        cudaFuncSetAttribute(edge_mma_kernel, cudaFuncAttributeMaxDynamicSharedMemorySize, EDGE_SMEM_BYTES);
        cudaFuncSetAttribute(node_proj_kernel, cudaFuncAttributeMaxDynamicSharedMemorySize, NODE_SMEM_BYTES);
        attr_set = true;
    }

    {   // 1
        int grid = (total4 + 255) / 256;
        if (grid > 1024) grid = 1024;
        zero_kernel<<<grid, 256>>>(total4);
    }
    {   // 2
        dim3 grid((n_nodes + 127) / 128, 2);
        node_proj_kernel<<<grid, 256, NODE_SMEM_BYTES>>>(x, Wf, Ws, n_nodes);
    }
    prep_B_kernel<<<32, 256>>>(Wf, Ws);                                      // 3
    {   // 4  <- ncu slot
        int grid = (n_edges + TILE_E - 1) / TILE_E;
        edge_mma_kernel<<<grid, 256, EDGE_SMEM_BYTES>>>(ea, bf, bs, esrc, etgt, n_edges);
    }
    stats_kernel<<<512, 256>>>(total4);                                      // 5
    {   // 6
        int grid = (total4 + 255) / 256;
        final_kernel<<<grid, 256>>>(x, gamma, beta, out, total4, 1.0f / (float)n_nodes);
    }
}

// round 7
// speedup vs baseline: 5.6858x; 1.1225x over previous
#include <cuda_runtime.h>
#include <cuda_fp16.h>
#include <math.h>

#define DCH    64
#define FAN    192
#define TILE_E 128
#define MAX_NODES 50176

__device__ float g_message[MAX_NODES * DCH];
__device__ float g_P1[MAX_NODES * 128];
__device__ float g_P2[MAX_NODES * 128];
__device__ float g_sum[DCH];
__device__ float g_sumsq[DCH];
// W slices interleaved [n=2d+gv][k], fp16 hi/lo; slice 0: W cols 0..63 (src),
// slice 1: 64..127 (tgt), slice 2: 128..191 (edge_attr)
__device__ unsigned short g_Bh[3 * 128 * 64];
__device__ unsigned short g_Bl[3 * 128 * 64];

// ---------------- edge kernel smem (bytes) ----------------
#define EO_SRC   0
#define EO_TGT   512
#define EO_AH    1024
#define EO_STAGE 17408
#define STG      68
#define EO_BH    52224            // 17408 + 128*68*4
#define EO_BL    68608
#define EDGE_SMEM_BYTES 84992

// ---------------- node kernel smem ----------------
#define NO_AH    0
#define NO_AL    16384
#define NO_BH    32768
#define NO_BL    49152
#define NODE_SMEM_BYTES 65536

// ---------------- helpers ----------------
__device__ __forceinline__ unsigned smem_u32(const void* p) {
    unsigned a;
    asm("{ .reg .u64 t; cvta.to.shared.u64 t, %1; cvt.u32.u64 %0, t; }" : "=r"(a) : "l"(p));
    return a;
}
__device__ __forceinline__ unsigned pack_f16x2(float lo, float hi) {
    unsigned r;
    asm("cvt.rn.f16x2.f32 %0, %1, %2;" : "=r"(r) : "f"(hi), "f"(lo));
    return r;
}
__device__ __forceinline__ float ex2a(float x) { float r; asm("ex2.approx.f32 %0, %1;" : "=f"(r) : "f"(x)); return r; }
__device__ __forceinline__ float lg2a(float x) { float r; asm("lg2.approx.f32 %0, %1;" : "=f"(r) : "f"(x)); return r; }
__device__ __forceinline__ float rcpa(float x) { float r; asm("rcp.approx.f32 %0, %1;" : "=f"(r) : "f"(x)); return r; }
__device__ __forceinline__ float sigmoid_f(float g) {
    return rcpa(1.0f + ex2a(-1.44269504f * g));
}
__device__ __forceinline__ float softplus_f(float v) {
    float u = ex2a(-1.44269504f * fabsf(v));
    return fmaxf(v, 0.0f) + 0.69314718f * lg2a(1.0f + u);
}

#define LDSM4(R, A) \
    asm volatile("ldmatrix.sync.aligned.m8n8.x4.shared.b16 {%0,%1,%2,%3}, [%4];" \
        : "=r"((R)[0]), "=r"((R)[1]), "=r"((R)[2]), "=r"((R)[3]) : "r"(A))
#define LDSM2(R0, R1, A) \
    asm volatile("ldmatrix.sync.aligned.m8n8.x2.shared.b16 {%0,%1}, [%2];" \
        : "=r"(R0), "=r"(R1) : "r"(A))
#define MMA16816(D, A, B0, B1) \
    asm volatile("mma.sync.aligned.m16n8k16.row.col.f32.f16.f16.f32 " \
        "{%0,%1,%2,%3}, {%4,%5,%6,%7}, {%8,%9}, {%0,%1,%2,%3};" \
        : "+f"((D)[0]), "+f"((D)[1]), "+f"((D)[2]), "+f"((D)[3]) \
        : "r"((A)[0]), "r"((A)[1]), "r"((A)[2]), "r"((A)[3]), "r"(B0), "r"(B1))

// ---------------- prep: all 3 W slices -> fp16 hi/lo ----------------
__global__ void prep_B_kernel(const float* __restrict__ Wf, const float* __restrict__ Ws) {
    int idx = blockIdx.x * 256 + threadIdx.x;   // 24576
    int s = idx >> 13;
    int r = idx & 8191;
    int n = r >> 6;
    int k = r & 63;
    int d = n >> 1;
    const float* w = (n & 1) ? Ws : Wf;
    float v = w[d * FAN + s * 64 + k];
    __half h = __float2half_rn(v);
    __half l = __float2half_rn(v - __half2float(h));
    g_Bh[idx] = __half_as_ushort(h);
    g_Bl[idx] = __half_as_ushort(l);
}

// ---------------- zero ----------------
__global__ void zero_kernel(int total4) {
    int i = blockIdx.x * blockDim.x + threadIdx.x;
    int stride = gridDim.x * blockDim.x;
    float4* m4 = (float4*)g_message;
    for (int j = i; j < total4; j += stride) m4[j] = make_float4(0.f, 0.f, 0.f, 0.f);
    if (i < DCH) { g_sum[i] = 0.0f; g_sumsq[i] = 0.0f; }
}

// ---------------- node projections on tensor cores ----------------
// grid (148, 2): y = wsel (0 -> P1 / W slice 0, 1 -> P2 / W slice 1)
__global__ __launch_bounds__(256, 2)
void node_mma_kernel(const float* __restrict__ x, int n_nodes, int ntiles)
{
    extern __shared__ char smc[];
    unsigned sb = smem_u32(smc);
    const int tid = threadIdx.x;
    const int wsel = blockIdx.y;
    float* P = wsel ? g_P2 : g_P1;

    // ---- B tiles once (hi + lo), swizzled ----
    {
        const uint4* bh = (const uint4*)g_Bh + wsel * 1024;
        const uint4* bl = (const uint4*)g_Bl + wsel * 1024;
        #pragma unroll
        for (int j = 0; j < 4; j++) {
            int idx = tid + j * 256;
            int n = idx >> 3;
            int cj = idx & 7;
            unsigned dst = n * 128 + ((cj * 16) ^ ((n & 7) << 4));
            *(uint4*)(smc + NO_BH + dst) = bh[idx];
            *(uint4*)(smc + NO_BL + dst) = bl[idx];
        }
    }

    const int w = tid >> 5;
    const int lane = tid & 31;
    const int m0 = (w & 3) * 32;
    const int nn0 = (w >> 2) * 64;
    const int rA0 = m0 + (lane & 15);
    const unsigned hiA = ((lane >> 4) & 1) << 4;
    const unsigned swA = (rA0 & 7) << 4;
    const int rB = nn0 + (lane & 7);
    const unsigned hiB = ((lane >> 3) & 1) << 4;
    const unsigned swB = (lane & 7) << 4;
    const unsigned boff = sb + NO_BH + rB * 128;
    const int cq = lane & 3;
    const int cbase = (w >> 2) * 32;

    for (int t = blockIdx.x; t < ntiles; t += 148) {
        int n0 = t * 128;
        __syncthreads();
        // ---- A tiles: x -> fp16 hi/lo, swizzled ----
        #pragma unroll
        for (int j = 0; j < 4; j++) {
            int idx = tid + j * 256;
            int e = idx >> 3;
            int cj = idx & 7;
            float4 v0, v1;
            if (n0 + e < n_nodes) {
                const float4* src = (const float4*)x + (size_t)(n0 + e) * 16 + cj * 2;
                v0 = src[0]; v1 = src[1];
            } else {
                v0 = make_float4(0.f, 0.f, 0.f, 0.f);
                v1 = v0;
            }
            float vv[8] = {v0.x, v0.y, v0.z, v0.w, v1.x, v1.y, v1.z, v1.w};
            unsigned H[4], L[4];
            #pragma unroll
            for (int p = 0; p < 4; p++) {
                __half h0 = __float2half_rn(vv[2 * p]);
                __half h1 = __float2half_rn(vv[2 * p + 1]);
                __half l0 = __float2half_rn(vv[2 * p] - __half2float(h0));
                __half l1 = __float2half_rn(vv[2 * p + 1] - __half2float(h1));
                H[p] = (unsigned)__half_as_ushort(h0) | ((unsigned)__half_as_ushort(h1) << 16);
                L[p] = (unsigned)__half_as_ushort(l0) | ((unsigned)__half_as_ushort(l1) << 16);
            }
            unsigned dst = e * 128 + ((cj * 16) ^ ((e & 7) << 4));
            *(uint4*)(smc + NO_AH + dst) = make_uint4(H[0], H[1], H[2], H[3]);
            *(uint4*)(smc + NO_AL + dst) = make_uint4(L[0], L[1], L[2], L[3]);
        }
        __syncthreads();

        float acc[2][8][4];
        #pragma unroll
        for (int mt = 0; mt < 2; mt++)
            #pragma unroll
            for (int nt = 0; nt < 8; nt++)
                #pragma unroll
                for (int p = 0; p < 4; p++) acc[mt][nt][p] = 0.0f;

        const unsigned aoff0 = sb + NO_AH + rA0 * 128;
        const unsigned aoff1 = aoff0 + 16 * 128;
        #pragma unroll
        for (int kc = 0; kc < 4; kc++) {
            unsigned ka = (unsigned)(kc * 32 + hiA) ^ swA;
            unsigned ah[4], ah2[4], al[4], al2[4];
            LDSM4(ah,  aoff0 + ka);
            LDSM4(ah2, aoff1 + ka);
            LDSM4(al,  aoff0 + ka + 16384);
            LDSM4(al2, aoff1 + ka + 16384);
            unsigned kb = (unsigned)(kc * 32 + hiB) ^ swB;
            #pragma unroll
            for (int nt = 0; nt < 8; nt++) {
                unsigned ba = boff + nt * 8 * 128 + kb;
                unsigned bh0, bh1, bl0, bl1;
                LDSM2(bh0, bh1, ba);
                LDSM2(bl0, bl1, ba + 16384);
                MMA16816(acc[0][nt], ah,  bh0, bh1);
                MMA16816(acc[1][nt], ah2, bh0, bh1);
                MMA16816(acc[0][nt], ah,  bl0, bl1);
                MMA16816(acc[1][nt], ah2, bl0, bl1);
                MMA16816(acc[0][nt], al,  bh0, bh1);
                MMA16816(acc[1][nt], al2, bh0, bh1);
            }
        }

        // ---- write P (coalesced-ish float2 stores) ----
        #pragma unroll
        for (int mt = 0; mt < 2; mt++) {
            int elo = m0 + mt * 16 + (lane >> 2);
            int ehi = elo + 8;
            #pragma unroll
            for (int nt = 0; nt < 8; nt++) {
                int c2 = 2 * (cbase + nt * 4 + cq);
                if (n0 + elo < n_nodes)
                    *(float2*)(P + (size_t)(n0 + elo) * 128 + c2) = make_float2(acc[mt][nt][0], acc[mt][nt][1]);
                if (n0 + ehi < n_nodes)
                    *(float2*)(P + (size_t)(n0 + ehi) * 128 + c2) = make_float2(acc[mt][nt][2], acc[mt][nt][3]);
            }
        }
    }
}

// ---------------- edge kernel: persistent, fp16 2-term mma ----------------
__global__ __launch_bounds__(256, 2)
void edge_mma_kernel(const float* __restrict__ ea,
                     const float* __restrict__ bfb,
                     const float* __restrict__ bsb,
                     const int*   __restrict__ esrc,
                     const int*   __restrict__ etgt,
                     int n_edges, int ntiles)
{
    extern __shared__ char smc[];
    unsigned sb = smem_u32(smc);
    int* s_src = (int*)(smc + EO_SRC);
    int* s_tgt = (int*)(smc + EO_TGT);
    float* stage = (float*)(smc + EO_STAGE);
    const int tid = threadIdx.x;

    // ---- B tiles once (slice 2), swizzled ----
    {
        const uint4* bh = (const uint4*)g_Bh + 2 * 1024;
        const uint4* bl = (const uint4*)g_Bl + 2 * 1024;
        #pragma unroll
        for (int j = 0; j < 4; j++) {
            int idx = tid + j * 256;
            int n = idx >> 3;
            int cj = idx & 7;
            unsigned dst = n * 128 + ((cj * 16) ^ ((n & 7) << 4));
            *(uint4*)(smc + EO_BH + dst) = bh[idx];
            *(uint4*)(smc + EO_BL + dst) = bl[idx];
        }
    }

    const int w = tid >> 5;
    const int lane = tid & 31;
    const int m0 = (w & 3) * 32;
    const int nn0 = (w >> 2) * 64;
    const int rA0 = m0 + (lane & 15);
    const unsigned hiA = ((lane >> 4) & 1) << 4;
    const unsigned swA = (rA0 & 7) << 4;
    const unsigned aoff0 = sb + EO_AH + rA0 * 128;
    const unsigned aoff1 = aoff0 + 16 * 128;
    const int rB = nn0 + (lane & 7);
    const unsigned hiB = ((lane >> 3) & 1) << 4;
    const unsigned swB = (lane & 7) << 4;
    const unsigned boff = sb + EO_BH + rB * 128;
    const int cq = lane & 3;
    const int cbase = (w >> 2) * 32;

    // bias hoisted (constant per thread across tiles)
    float bfv[8], bsv[8];
    #pragma unroll
    for (int nt = 0; nt < 8; nt++) {
        int c = cbase + nt * 4 + cq;
        bfv[nt] = bfb[c];
        bsv[nt] = bsb[c];
    }

    for (int t = blockIdx.x; t < ntiles; t += gridDim.x) {
        const int e0 = t * TILE_E;
        __syncthreads();   // protect A/idx/stage from previous iteration readers

        // ---- A tile: ea -> fp16 hi, swizzled ----
        #pragma unroll
        for (int j = 0; j < 4; j++) {
            int idx = tid + j * 256;
            int e = idx >> 3;
            int cj = idx & 7;
            int ge = e0 + e;
            float4 v0, v1;
            if (ge < n_edges) {
                const float4* src = (const float4*)ea + (size_t)ge * 16 + cj * 2;
                v0 = src[0]; v1 = src[1];
            } else {
                v0 = make_float4(0.f, 0.f, 0.f, 0.f);
                v1 = v0;
            }
            unsigned H[4];
            H[0] = pack_f16x2(v0.x, v0.y);
            H[1] = pack_f16x2(v0.z, v0.w);
            H[2] = pack_f16x2(v1.x, v1.y);
            H[3] = pack_f16x2(v1.z, v1.w);
            unsigned dst = e * 128 + ((cj * 16) ^ ((e & 7) << 4));
            *(uint4*)(smc + EO_AH + dst) = make_uint4(H[0], H[1], H[2], H[3]);
        }
        if (tid < TILE_E) {
            int ge = e0 + tid;
            s_src[tid] = (ge < n_edges) ? esrc[ge] : 0;
            s_tgt[tid] = (ge < n_edges) ? etgt[ge] : 0;
        }
        __syncthreads();

        // ---- mma mainloop (A hi x B hi + A hi x B lo) ----
        float acc[2][8][4];
        #pragma unroll
        for (int mt = 0; mt < 2; mt++)
            #pragma unroll
            for (int nt = 0; nt < 8; nt++)
                #pragma unroll
                for (int p = 0; p < 4; p++) acc[mt][nt][p] = 0.0f;

        #pragma unroll
        for (int kc = 0; kc < 4; kc++) {
            unsigned ka = (unsigned)(kc * 32 + hiA) ^ swA;
            unsigned ah[4], ah2[4];
            LDSM4(ah,  aoff0 + ka);
            LDSM4(ah2, aoff1 + ka);
            unsigned kb = (unsigned)(kc * 32 + hiB) ^ swB;
            #pragma unroll
            for (int nt = 0; nt < 8; nt++) {
                unsigned ba = boff + nt * 8 * 128 + kb;
                unsigned bh0, bh1, bl0, bl1;
                LDSM2(bh0, bh1, ba);
                LDSM2(bl0, bl1, ba + 16384);
                MMA16816(acc[0][nt], ah,  bh0, bh1);
                MMA16816(acc[1][nt], ah2, bh0, bh1);
                MMA16816(acc[0][nt], ah,  bl0, bl1);
                MMA16816(acc[1][nt], ah2, bl0, bl1);
            }
        }

        // ---- epilogue: batched P gathers + activation -> stage ----
        #pragma unroll
        for (int mt = 0; mt < 2; mt++) {
            int elo = m0 + mt * 16 + (lane >> 2);
            int ehi = elo + 8;
            const float* P1l = g_P1 + (size_t)s_src[elo] * 128;
            const float* P2l = g_P2 + (size_t)s_tgt[elo] * 128;
            const float* P1h = g_P1 + (size_t)s_src[ehi] * 128;
            const float* P2h = g_P2 + (size_t)s_tgt[ehi] * 128;
            float2 a1[8], a2[8];
            #pragma unroll
            for (int nt = 0; nt < 8; nt++) {
                int c2 = 2 * (cbase + nt * 4 + cq);
                a1[nt] = *(const float2*)(P1l + c2);
                a2[nt] = *(const float2*)(P2l + c2);
            }
            #pragma unroll
            for (int nt = 0; nt < 8; nt++) {
                int c = cbase + nt * 4 + cq;
                float g = acc[mt][nt][0] + a1[nt].x + a2[nt].x + bfv[nt];
                float v = acc[mt][nt][1] + a1[nt].y + a2[nt].y + bsv[nt];
                stage[elo * STG + c] = sigmoid_f(g) * softplus_f(v);
            }
            #pragma unroll
            for (int nt = 0; nt < 8; nt++) {
                int c2 = 2 * (cbase + nt * 4 + cq);
                a1[nt] = *(const float2*)(P1h + c2);
                a2[nt] = *(const float2*)(P2h + c2);
            }
            #pragma unroll
            for (int nt = 0; nt < 8; nt++) {
                int c = cbase + nt * 4 + cq;
                float g = acc[mt][nt][2] + a1[nt].x + a2[nt].x + bfv[nt];
                float v = acc[mt][nt][3] + a1[nt].y + a2[nt].y + bsv[nt];
                stage[ehi * STG + c] = sigmoid_f(g) * softplus_f(v);
            }
        }
        __syncthreads();

        // ---- scatter ----
        {
            int e = tid >> 1;
            int half = tid & 1;
            int ge = e0 + e;
            if (ge < n_edges) {
                float* dst = g_message + (size_t)s_src[e] * 64 + half * 32;
                const float* srow = stage + e * STG + half * 32;
                #pragma unroll
                for (int q = 0; q < 8; q++) {
                    float4 v = *(const float4*)(srow + q * 4);
                    asm volatile("red.global.add.v4.f32 [%0], {%1, %2, %3, %4};"
                                 :: "l"(dst + q * 4), "f"(v.x), "f"(v.y), "f"(v.z), "f"(v.w)
                                 : "memory");
                }
            }
        }
    }
}

// ---------------- stats ----------------
__global__ __launch_bounds__(256)
void stats_kernel(int n4) {
    int t = blockIdx.x * blockDim.x + threadIdx.x;
    int stride = gridDim.x * blockDim.x;
    const float4* m4 = (const float4*)g_message;
    float4 s = make_float4(0.f, 0.f, 0.f, 0.f);
    float4 q = make_float4(0.f, 0.f, 0.f, 0.f);
    for (int i = t; i < n4; i += stride) {
        float4 v = m4[i];
        s.x += v.x; s.y += v.y; s.z += v.z; s.w += v.w;
        q.x += v.x * v.x; q.y += v.y * v.y; q.z += v.z * v.z; q.w += v.w * v.w;
    }
    __shared__ float4 ss[256];
    __shared__ float4 qq[256];
    ss[threadIdx.x] = s;
    qq[threadIdx.x] = q;
    __syncthreads();
    #pragma unroll
    for (int off = 128; off >= 16; off >>= 1) {
        if (threadIdx.x < off) {
            float4 a = ss[threadIdx.x + off], b = qq[threadIdx.x + off];
            float4 sa = ss[threadIdx.x], qa = qq[threadIdx.x];
            sa.x += a.x; sa.y += a.y; sa.z += a.z; sa.w += a.w;
            qa.x += b.x; qa.y += b.y; qa.z += b.z; qa.w += b.w;
            ss[threadIdx.x] = sa;
            qq[threadIdx.x] = qa;
        }
        __syncthreads();
    }
    if (threadIdx.x < 16) {
        int c = threadIdx.x * 4;
        float4 sa = ss[threadIdx.x], qa = qq[threadIdx.x];
        atomicAdd(&g_sum[c + 0], sa.x); atomicAdd(&g_sum[c + 1], sa.y);
        atomicAdd(&g_sum[c + 2], sa.z); atomicAdd(&g_sum[c + 3], sa.w);
        atomicAdd(&g_sumsq[c + 0], qa.x); atomicAdd(&g_sumsq[c + 1], qa.y);
        atomicAdd(&g_sumsq[c + 2], qa.z); atomicAdd(&g_sumsq[c + 3], qa.w);
    }
}

// ---------------- final ----------------
__global__ __launch_bounds__(256)
void final_kernel(const float* __restrict__ x,
                  const float* __restrict__ gamma,
                  const float* __restrict__ beta,
                  float* __restrict__ out,
                  int n4, float inv_n)
{
    int i = blockIdx.x * blockDim.x + threadIdx.x;
    if (i >= n4) return;
    int c = (i & 15) * 4;
    float4 mm = ((const float4*)g_message)[i];
    float4 xx = ((const float4*)x)[i];
    float4 gm = ((const float4*)gamma)[i & 15];
    float4 bt = ((const float4*)beta)[i & 15];
    float mv[4] = {mm.x, mm.y, mm.z, mm.w};
    float xv[4] = {xx.x, xx.y, xx.z, xx.w};
    float gv[4] = {gm.x, gm.y, gm.z, gm.w};
    float bv[4] = {bt.x, bt.y, bt.z, bt.w};
    float ov[4];
    #pragma unroll
    for (int j = 0; j < 4; j++) {
        float mean = g_sum[c + j] * inv_n;
        float var  = g_sumsq[c + j] * inv_n - mean * mean;
        float inv_std = rsqrtf(var + 1e-5f);
        float mn = (mv[j] - mean) * inv_std * gv[j] + bv[j];
        float t = xv[j] + mn;
        ov[j] = fmaxf(t, 0.0f) + log1pf(expf(-fabsf(t)));
    }
    ((float4*)out)[i] = make_float4(ov[0], ov[1], ov[2], ov[3]);
}

extern "C" void kernel_launch(void* const* d_in, const int* in_sizes, int n_in,
                              void* d_out, int out_size)
{
    const float* x     = (const float*)d_in[0];
    const float* ea    = (const float*)d_in[1];
    const float* Wf    = (const float*)d_in[2];
    const float* bf    = (const float*)d_in[3];
    const float* Ws    = (const float*)d_in[4];
    const float* bs    = (const float*)d_in[5];
    const float* gamma = (const float*)d_in[6];
    const float* beta  = (const float*)d_in[7];
    const int*   esrc  = (const int*)d_in[8];
    const int*   etgt  = (const int*)d_in[9];
    float* out = (float*)d_out;

    int n_nodes = in_sizes[0] / DCH;
    int n_edges = in_sizes[8];
    int total   = n_nodes * DCH;
    int total4  = total / 4;
    int etiles  = (n_edges + TILE_E - 1) / TILE_E;
    int ntiles  = (n_nodes + 127) / 128;

    static bool attr_set = false;
    if (!attr_set) {
        cudaFuncSetAttribute(edge_mma_kernel, cudaFuncAttributeMaxDynamicSharedMemorySize, EDGE_SMEM_BYTES);
        cudaFuncSetAttribute(node_mma_kernel, cudaFuncAttributeMaxDynamicSharedMemorySize, NODE_SMEM_BYTES);
        attr_set = true;
    }

    {   // 1
        int grid = (total4 + 255) / 256;
        if (grid > 1024) grid = 1024;
        zero_kernel<<<grid, 256>>>(total4);
    }
    prep_B_kernel<<<96, 256>>>(Wf, Ws);                                      // 2
    {   // 3
        dim3 grid(148, 2);
        node_mma_kernel<<<grid, 256, NODE_SMEM_BYTES>>>(x, n_nodes, ntiles);
    }
    {   // 4  <- ncu slot
        int grid = 296;
        if (grid > etiles) grid = etiles;
        edge_mma_kernel<<<grid, 256, EDGE_SMEM_BYTES>>>(ea, bf, bs, esrc, etgt, n_edges, etiles);
    }
    stats_kernel<<<512, 256>>>(total4);                                      // 5
    {   // 6
        int grid = (total4 + 255) / 256;
        final_kernel<<<grid, 256>>>(x, gamma, beta, out, total4, 1.0f / (float)n_nodes);
    }
}

// round 8
// speedup vs baseline: 7.0364x; 1.2375x over previous
#include <cuda_runtime.h>
#include <cuda_fp16.h>
#include <math.h>

#define DCH    64
#define FAN    192
#define TILE_E 128
#define MAX_NODES 50176

__device__ float g_message[MAX_NODES * DCH];
__device__ unsigned short g_P1h[MAX_NODES * 128];   // fp16 (g,v) interleaved per channel
__device__ unsigned short g_P2h[MAX_NODES * 128];
__device__ float g_sum[DCH];
__device__ float g_sumsq[DCH];
__device__ unsigned short g_Bh[3 * 128 * 64];
__device__ unsigned short g_Bl[3 * 128 * 64];

// ---------------- edge kernel smem (bytes) ----------------
#define EO_SRC   0
#define EO_TGT   512
#define EO_BF    1024
#define EO_BS    1280
#define EO_AH    1536
#define EO_STAGE 17920            // 64 edges x 66 float2 = 33792 B
#define STG2     66               // stage row stride in float2
#define EO_BH    51712
#define EO_BL    68096
#define EDGE_SMEM_BYTES 84480

// ---------------- node kernel smem ----------------
#define NO_AH    0
#define NO_AL    16384
#define NO_BH    32768
#define NO_BL    49152
#define NODE_SMEM_BYTES 65536

// ---------------- helpers ----------------
__device__ __forceinline__ unsigned smem_u32(const void* p) {
    unsigned a;
    asm("{ .reg .u64 t; cvta.to.shared.u64 t, %1; cvt.u32.u64 %0, t; }" : "=r"(a) : "l"(p));
    return a;
}
__device__ __forceinline__ unsigned pack_f16x2(float lo, float hi) {
    unsigned r;
    asm("cvt.rn.f16x2.f32 %0, %1, %2;" : "=r"(r) : "f"(hi), "f"(lo));
    return r;
}
__device__ __forceinline__ float2 unpack_h2(unsigned u) {
    __half2 h = *reinterpret_cast<__half2*>(&u);
    return __half22float2(h);
}
__device__ __forceinline__ float ex2a(float x) { float r; asm("ex2.approx.f32 %0, %1;" : "=f"(r) : "f"(x)); return r; }
__device__ __forceinline__ float lg2a(float x) { float r; asm("lg2.approx.f32 %0, %1;" : "=f"(r) : "f"(x)); return r; }
__device__ __forceinline__ float rcpa(float x) { float r; asm("rcp.approx.f32 %0, %1;" : "=f"(r) : "f"(x)); return r; }
__device__ __forceinline__ float sigmoid_f(float g) {
    return rcpa(1.0f + ex2a(-1.44269504f * g));
}
__device__ __forceinline__ float softplus_f(float v) {
    float u = ex2a(-1.44269504f * fabsf(v));
    return fmaxf(v, 0.0f) + 0.69314718f * lg2a(1.0f + u);
}

#define LDSM4(R, A) \
    asm volatile("ldmatrix.sync.aligned.m8n8.x4.shared.b16 {%0,%1,%2,%3}, [%4];" \
        : "=r"((R)[0]), "=r"((R)[1]), "=r"((R)[2]), "=r"((R)[3]) : "r"(A))
#define LDSM2(R0, R1, A) \
    asm volatile("ldmatrix.sync.aligned.m8n8.x2.shared.b16 {%0,%1}, [%2];" \
        : "=r"(R0), "=r"(R1) : "r"(A))
#define MMA16816(D, A, B0, B1) \
    asm volatile("mma.sync.aligned.m16n8k16.row.col.f32.f16.f16.f32 " \
        "{%0,%1,%2,%3}, {%4,%5,%6,%7}, {%8,%9}, {%0,%1,%2,%3};" \
        : "+f"((D)[0]), "+f"((D)[1]), "+f"((D)[2]), "+f"((D)[3]) \
        : "r"((A)[0]), "r"((A)[1]), "r"((A)[2]), "r"((A)[3]), "r"(B0), "r"(B1))

// ---------------- prep: all 3 W slices -> fp16 hi/lo ----------------
__global__ void prep_B_kernel(const float* __restrict__ Wf, const float* __restrict__ Ws) {
    int idx = blockIdx.x * 256 + threadIdx.x;   // 24576
    int s = idx >> 13;
    int r = idx & 8191;
    int n = r >> 6;
    int k = r & 63;
    int d = n >> 1;
    const float* w = (n & 1) ? Ws : Wf;
    float v = w[d * FAN + s * 64 + k];
    __half h = __float2half_rn(v);
    __half l = __float2half_rn(v - __half2float(h));
    g_Bh[idx] = __half_as_ushort(h);
    g_Bl[idx] = __half_as_ushort(l);
}

// ---------------- zero ----------------
__global__ void zero_kernel(int total4) {
    int i = blockIdx.x * blockDim.x + threadIdx.x;
    int stride = gridDim.x * blockDim.x;
    float4* m4 = (float4*)g_message;
    for (int j = i; j < total4; j += stride) m4[j] = make_float4(0.f, 0.f, 0.f, 0.f);
    if (i < DCH) { g_sum[i] = 0.0f; g_sumsq[i] = 0.0f; }
}

// ---------------- node projections on tensor cores -> fp16 P ----------------
__global__ __launch_bounds__(256, 2)
void node_mma_kernel(const float* __restrict__ x, int n_nodes, int ntiles)
{
    extern __shared__ char smc[];
    unsigned sb = smem_u32(smc);
    const int tid = threadIdx.x;
    const int wsel = blockIdx.y;
    unsigned short* P = wsel ? g_P2h : g_P1h;

    {
        const uint4* bh = (const uint4*)g_Bh + wsel * 1024;
        const uint4* bl = (const uint4*)g_Bl + wsel * 1024;
        #pragma unroll
        for (int j = 0; j < 4; j++) {
            int idx = tid + j * 256;
            int n = idx >> 3;
            int cj = idx & 7;
            unsigned dst = n * 128 + ((cj * 16) ^ ((n & 7) << 4));
            *(uint4*)(smc + NO_BH + dst) = bh[idx];
            *(uint4*)(smc + NO_BL + dst) = bl[idx];
        }
    }

    const int w = tid >> 5;
    const int lane = tid & 31;
    const int m0 = (w & 3) * 32;
    const int nn0 = (w >> 2) * 64;
    const int rA0 = m0 + (lane & 15);
    const unsigned hiA = ((lane >> 4) & 1) << 4;
    const unsigned swA = (rA0 & 7) << 4;
    const int rB = nn0 + (lane & 7);
    const unsigned hiB = ((lane >> 3) & 1) << 4;
    const unsigned swB = (lane & 7) << 4;
    const unsigned boff = sb + NO_BH + rB * 128;
    const int cq = lane & 3;
    const int cbase = (w >> 2) * 32;

    for (int t = blockIdx.x; t < ntiles; t += 148) {
        int n0 = t * 128;
        __syncthreads();
        #pragma unroll
        for (int j = 0; j < 4; j++) {
            int idx = tid + j * 256;
            int e = idx >> 3;
            int cj = idx & 7;
            float4 v0, v1;
            if (n0 + e < n_nodes) {
                const float4* src = (const float4*)x + (size_t)(n0 + e) * 16 + cj * 2;
                v0 = src[0]; v1 = src[1];
            } else {
                v0 = make_float4(0.f, 0.f, 0.f, 0.f);
                v1 = v0;
            }
            float vv[8] = {v0.x, v0.y, v0.z, v0.w, v1.x, v1.y, v1.z, v1.w};
            unsigned H[4], L[4];
            #pragma unroll
            for (int p = 0; p < 4; p++) {
                __half h0 = __float2half_rn(vv[2 * p]);
                __half h1 = __float2half_rn(vv[2 * p + 1]);
                __half l0 = __float2half_rn(vv[2 * p] - __half2float(h0));
                __half l1 = __float2half_rn(vv[2 * p + 1] - __half2float(h1));
                H[p] = (unsigned)__half_as_ushort(h0) | ((unsigned)__half_as_ushort(h1) << 16);
                L[p] = (unsigned)__half_as_ushort(l0) | ((unsigned)__half_as_ushort(l1) << 16);
            }
            unsigned dst = e * 128 + ((cj * 16) ^ ((e & 7) << 4));
            *(uint4*)(smc + NO_AH + dst) = make_uint4(H[0], H[1], H[2], H[3]);
            *(uint4*)(smc + NO_AL + dst) = make_uint4(L[0], L[1], L[2], L[3]);
        }
        __syncthreads();

        float acc[2][8][4];
        #pragma unroll
        for (int mt = 0; mt < 2; mt++)
            #pragma unroll
            for (int nt = 0; nt < 8; nt++)
                #pragma unroll
                for (int p = 0; p < 4; p++) acc[mt][nt][p] = 0.0f;

        const unsigned aoff0 = sb + NO_AH + rA0 * 128;
        const unsigned aoff1 = aoff0 + 16 * 128;
        #pragma unroll
        for (int kc = 0; kc < 4; kc++) {
            unsigned ka = (unsigned)(kc * 32 + hiA) ^ swA;
            unsigned ah[4], ah2[4], al[4], al2[4];
            LDSM4(ah,  aoff0 + ka);
            LDSM4(ah2, aoff1 + ka);
            LDSM4(al,  aoff0 + ka + 16384);
            LDSM4(al2, aoff1 + ka + 16384);
            unsigned kb = (unsigned)(kc * 32 + hiB) ^ swB;
            #pragma unroll
            for (int nt = 0; nt < 8; nt++) {
                unsigned ba = boff + nt * 8 * 128 + kb;
                unsigned bh0, bh1, bl0, bl1;
                LDSM2(bh0, bh1, ba);
                LDSM2(bl0, bl1, ba + 16384);
                MMA16816(acc[0][nt], ah,  bh0, bh1);
                MMA16816(acc[1][nt], ah2, bh0, bh1);
                MMA16816(acc[0][nt], ah,  bl0, bl1);
                MMA16816(acc[1][nt], ah2, bl0, bl1);
                MMA16816(acc[0][nt], al,  bh0, bh1);
                MMA16816(acc[1][nt], al2, bh0, bh1);
            }
        }

        #pragma unroll
        for (int mt = 0; mt < 2; mt++) {
            int elo = m0 + mt * 16 + (lane >> 2);
            int ehi = elo + 8;
            #pragma unroll
            for (int nt = 0; nt < 8; nt++) {
                int c = cbase + nt * 4 + cq;
                if (n0 + elo < n_nodes)
                    *(unsigned*)(P + (size_t)(n0 + elo) * 128 + 2 * c) = pack_f16x2(acc[mt][nt][0], acc[mt][nt][1]);
                if (n0 + ehi < n_nodes)
                    *(unsigned*)(P + (size_t)(n0 + ehi) * 128 + 2 * c) = pack_f16x2(acc[mt][nt][2], acc[mt][nt][3]);
            }
        }
    }
}

// ---------------- edge kernel ----------------
__global__ __launch_bounds__(256, 2)
void edge_mma_kernel(const float* __restrict__ ea,
                     const float* __restrict__ bfb,
                     const float* __restrict__ bsb,
                     const int*   __restrict__ esrc,
                     const int*   __restrict__ etgt,
                     int n_edges, int ntiles)
{
    extern __shared__ char smc[];
    unsigned sb = smem_u32(smc);
    int* s_src = (int*)(smc + EO_SRC);
    int* s_tgt = (int*)(smc + EO_TGT);
    float* s_bf = (float*)(smc + EO_BF);
    float* s_bs = (float*)(smc + EO_BS);
    float2* stage2 = (float2*)(smc + EO_STAGE);
    const int tid = threadIdx.x;

    // B tiles once
    {
        const uint4* bh = (const uint4*)g_Bh + 2 * 1024;
        const uint4* bl = (const uint4*)g_Bl + 2 * 1024;
        #pragma unroll
        for (int j = 0; j < 4; j++) {
            int idx = tid + j * 256;
            int n = idx >> 3;
            int cj = idx & 7;
            unsigned dst = n * 128 + ((cj * 16) ^ ((n & 7) << 4));
            *(uint4*)(smc + EO_BH + dst) = bh[idx];
            *(uint4*)(smc + EO_BL + dst) = bl[idx];
        }
    }
    if (tid < DCH) { s_bf[tid] = bfb[tid]; s_bs[tid] = bsb[tid]; }

    const int w = tid >> 5;
    const int lane = tid & 31;
    const int m0 = (w & 3) * 32;
    const int rA0 = m0 + (lane & 15);
    const unsigned hiA = ((lane >> 4) & 1) << 4;
    const unsigned swA = (rA0 & 7) << 4;
    const unsigned aoff0 = sb + EO_AH + rA0 * 128;
    const unsigned aoff1 = aoff0 + 16 * 128;
    const int rB = ((w >> 2) * 64) + (lane & 7);
    const unsigned hiB = ((lane >> 3) & 1) << 4;
    const unsigned swB = (lane & 7) << 4;
    const unsigned boff = sb + EO_BH + rB * 128;
    const int cq = lane & 3;
    const int cbase = (w >> 2) * 32;
    const int li = lane & 7;
    const int egl = lane >> 3;     // 0..3

    for (int t = blockIdx.x; t < ntiles; t += gridDim.x) {
        const int e0 = t * TILE_E;
        __syncthreads();

        // ---- A tile fill ----
        #pragma unroll
        for (int j = 0; j < 4; j++) {
            int idx = tid + j * 256;
            int e = idx >> 3;
            int cj = idx & 7;
            int ge = e0 + e;
            float4 v0, v1;
            if (ge < n_edges) {
                const float4* src = (const float4*)ea + (size_t)ge * 16 + cj * 2;
                v0 = src[0]; v1 = src[1];
            } else {
                v0 = make_float4(0.f, 0.f, 0.f, 0.f);
                v1 = v0;
            }
            unsigned H[4];
            H[0] = pack_f16x2(v0.x, v0.y);
            H[1] = pack_f16x2(v0.z, v0.w);
            H[2] = pack_f16x2(v1.x, v1.y);
            H[3] = pack_f16x2(v1.z, v1.w);
            unsigned dst = e * 128 + ((cj * 16) ^ ((e & 7) << 4));
            *(uint4*)(smc + EO_AH + dst) = make_uint4(H[0], H[1], H[2], H[3]);
        }
        if (tid < TILE_E) {
            int ge = e0 + tid;
            s_src[tid] = (ge < n_edges) ? esrc[ge] : 0;
            s_tgt[tid] = (ge < n_edges) ? etgt[ge] : 0;
        }
        __syncthreads();

        // ---- mma mainloop ----
        float acc[2][8][4];
        #pragma unroll
        for (int mt = 0; mt < 2; mt++)
            #pragma unroll
            for (int nt = 0; nt < 8; nt++)
                #pragma unroll
                for (int p = 0; p < 4; p++) acc[mt][nt][p] = 0.0f;

        #pragma unroll
        for (int kc = 0; kc < 4; kc++) {
            unsigned ka = (unsigned)(kc * 32 + hiA) ^ swA;
            unsigned ah[4], ah2[4];
            LDSM4(ah,  aoff0 + ka);
            LDSM4(ah2, aoff1 + ka);
            unsigned kb = (unsigned)(kc * 32 + hiB) ^ swB;
            #pragma unroll
            for (int nt = 0; nt < 8; nt++) {
                unsigned ba = boff + nt * 8 * 128 + kb;
                unsigned bh0, bh1, bl0, bl1;
                LDSM2(bh0, bh1, ba);
                LDSM2(bl0, bl1, ba + 16384);
                MMA16816(acc[0][nt], ah,  bh0, bh1);
                MMA16816(acc[1][nt], ah2, bh0, bh1);
                MMA16816(acc[0][nt], ah,  bl0, bl1);
                MMA16816(acc[1][nt], ah2, bl0, bl1);
            }
        }

        // ---- two half-tile epilogue phases ----
        #pragma unroll
        for (int ph = 0; ph < 2; ph++) {
            const int base = ph * 64;
            // store raw (g,v) for this half's edges
            if ((m0 < 64) == (ph == 0)) {
                #pragma unroll
                for (int mt = 0; mt < 2; mt++) {
                    int elo = m0 + mt * 16 + (lane >> 2) - base;
                    int ehi = elo + 8;
                    #pragma unroll
                    for (int nt = 0; nt < 8; nt++) {
                        int c = cbase + nt * 4 + cq;
                        stage2[elo * STG2 + c] = make_float2(acc[mt][nt][0], acc[mt][nt][1]);
                        stage2[ehi * STG2 + c] = make_float2(acc[mt][nt][2], acc[mt][nt][3]);
                    }
                }
            }
            __syncthreads();

            // per-edge contiguous gathers + activation + scatter
            #pragma unroll
            for (int g2 = 0; g2 < 2; g2++) {
                int el = base + w * 8 + g2 * 4 + egl;
                int srow = el - base;
                int ge = e0 + el;
                int src = s_src[el];
                int tgt = s_tgt[el];
                const unsigned short* P1r = g_P1h + (size_t)src * 128;
                const unsigned short* P2r = g_P2h + (size_t)tgt * 128;
                #pragma unroll
                for (int q = 0; q < 2; q++) {
                    int cc = q * 32 + li * 4;
                    float4 ra = *(const float4*)(stage2 + srow * STG2 + cc);
                    float4 rb = *(const float4*)(stage2 + srow * STG2 + cc + 2);
                    uint4 p1 = *(const uint4*)(P1r + 2 * cc);
                    uint4 p2 = *(const uint4*)(P2r + 2 * cc);
                    float4 bfv = *(const float4*)(s_bf + cc);
                    float4 bsv = *(const float4*)(s_bs + cc);
                    float2 q10 = unpack_h2(p1.x), q11 = unpack_h2(p1.y), q12 = unpack_h2(p1.z), q13 = unpack_h2(p1.w);
                    float2 q20 = unpack_h2(p2.x), q21 = unpack_h2(p2.y), q22 = unpack_h2(p2.z), q23 = unpack_h2(p2.w);
                    float m0v = sigmoid_f(ra.x + q10.x + q20.x + bfv.x) * softplus_f(ra.y + q10.y + q20.y + bsv.x);
                    float m1v = sigmoid_f(ra.z + q11.x + q21.x + bfv.y) * softplus_f(ra.w + q11.y + q21.y + bsv.y);
                    float m2v = sigmoid_f(rb.x + q12.x + q22.x + bfv.z) * softplus_f(rb.y + q12.y + q22.y + bsv.z);
                    float m3v = sigmoid_f(rb.z + q13.x + q23.x + bfv.w) * softplus_f(rb.w + q13.y + q23.y + bsv.w);
                    if (ge < n_edges) {
                        float* dst = g_message + (size_t)src * 64 + cc;
                        asm volatile("red.global.add.v4.f32 [%0], {%1, %2, %3, %4};"
                                     :: "l"(dst), "f"(m0v), "f"(m1v), "f"(m2v), "f"(m3v)
                                     : "memory");
                    }
                }
            }
            if (ph == 0) __syncthreads();
        }
    }
}

// ---------------- stats ----------------
__global__ __launch_bounds__(256)
void stats_kernel(int n4) {
    int t = blockIdx.x * blockDim.x + threadIdx.x;
    int stride = gridDim.x * blockDim.x;
    const float4* m4 = (const float4*)g_message;
    float4 s = make_float4(0.f, 0.f, 0.f, 0.f);
    float4 q = make_float4(0.f, 0.f, 0.f, 0.f);
    for (int i = t; i < n4; i += stride) {
        float4 v = m4[i];
        s.x += v.x; s.y += v.y; s.z += v.z; s.w += v.w;
        q.x += v.x * v.x; q.y += v.y * v.y; q.z += v.z * v.z; q.w += v.w * v.w;
    }
    __shared__ float4 ss[256];
    __shared__ float4 qq[256];
    ss[threadIdx.x] = s;
    qq[threadIdx.x] = q;
    __syncthreads();
    #pragma unroll
    for (int off = 128; off >= 16; off >>= 1) {
        if (threadIdx.x < off) {
            float4 a = ss[threadIdx.x + off], b = qq[threadIdx.x + off];
            float4 sa = ss[threadIdx.x], qa = qq[threadIdx.x];
            sa.x += a.x; sa.y += a.y; sa.z += a.z; sa.w += a.w;
            qa.x += b.x; qa.y += b.y; qa.z += b.z; qa.w += b.w;
            ss[threadIdx.x] = sa;
            qq[threadIdx.x] = qa;
        }
        __syncthreads();
    }
    if (threadIdx.x < 16) {
        int c = threadIdx.x * 4;
        float4 sa = ss[threadIdx.x], qa = qq[threadIdx.x];
        atomicAdd(&g_sum[c + 0], sa.x); atomicAdd(&g_sum[c + 1], sa.y);
        atomicAdd(&g_sum[c + 2], sa.z); atomicAdd(&g_sum[c + 3], sa.w);
        atomicAdd(&g_sumsq[c + 0], qa.x); atomicAdd(&g_sumsq[c + 1], qa.y);
        atomicAdd(&g_sumsq[c + 2], qa.z); atomicAdd(&g_sumsq[c + 3], qa.w);
    }
}

// ---------------- final ----------------
__global__ __launch_bounds__(256)
void final_kernel(const float* __restrict__ x,
                  const float* __restrict__ gamma,
                  const float* __restrict__ beta,
                  float* __restrict__ out,
                  int n4, float inv_n)
{
    int i = blockIdx.x * blockDim.x + threadIdx.x;
    if (i >= n4) return;
    int c = (i & 15) * 4;
    float4 mm = ((const float4*)g_message)[i];
    float4 xx = ((const float4*)x)[i];
    float4 gm = ((const float4*)gamma)[i & 15];
    float4 bt = ((const float4*)beta)[i & 15];
    float mv[4] = {mm.x, mm.y, mm.z, mm.w};
    float xv[4] = {xx.x, xx.y, xx.z, xx.w};
    float gv[4] = {gm.x, gm.y, gm.z, gm.w};
    float bv[4] = {bt.x, bt.y, bt.z, bt.w};
    float ov[4];
    #pragma unroll
    for (int j = 0; j < 4; j++) {
        float mean = g_sum[c + j] * inv_n;
        float var  = g_sumsq[c + j] * inv_n - mean * mean;
        float inv_std = rsqrtf(var + 1e-5f);
        float mn = (mv[j] - mean) * inv_std * gv[j] + bv[j];
        float t = xv[j] + mn;
        ov[j] = fmaxf(t, 0.0f) + log1pf(expf(-fabsf(t)));
    }
    ((float4*)out)[i] = make_float4(ov[0], ov[1], ov[2], ov[3]);
}

extern "C" void kernel_launch(void* const* d_in, const int* in_sizes, int n_in,
                              void* d_out, int out_size)
{
    const float* x     = (const float*)d_in[0];
    const float* ea    = (const float*)d_in[1];
    const float* Wf    = (const float*)d_in[2];
    const float* bf    = (const float*)d_in[3];
    const float* Ws    = (const float*)d_in[4];
    const float* bs    = (const float*)d_in[5];
    const float* gamma = (const float*)d_in[6];
    const float* beta  = (const float*)d_in[7];
    const int*   esrc  = (const int*)d_in[8];
    const int*   etgt  = (const int*)d_in[9];
    float* out = (float*)d_out;

    int n_nodes = in_sizes[0] / DCH;
    int n_edges = in_sizes[8];
    int total   = n_nodes * DCH;
    int total4  = total / 4;
    int etiles  = (n_edges + TILE_E - 1) / TILE_E;
    int ntiles  = (n_nodes + 127) / 128;

    static bool attr_set = false;
    if (!attr_set) {
        cudaFuncSetAttribute(edge_mma_kernel, cudaFuncAttributeMaxDynamicSharedMemorySize, EDGE_SMEM_BYTES);
        cudaFuncSetAttribute(node_mma_kernel, cudaFuncAttributeMaxDynamicSharedMemorySize, NODE_SMEM_BYTES);
        attr_set = true;
    }

    {   // 1
        int grid = (total4 + 255) / 256;
        if (grid > 1024) grid = 1024;
        zero_kernel<<<grid, 256>>>(total4);
    }
    prep_B_kernel<<<96, 256>>>(Wf, Ws);                                      // 2
    {   // 3
        dim3 grid(148, 2);
        node_mma_kernel<<<grid, 256, NODE_SMEM_BYTES>>>(x, n_nodes, ntiles);
    }
    {   // 4  <- ncu slot
        int grid = 296;
        if (grid > etiles) grid = etiles;
        edge_mma_kernel<<<grid, 256, EDGE_SMEM_BYTES>>>(ea, bf, bs, esrc, etgt, n_edges, etiles);
    }
    stats_kernel<<<512, 256>>>(total4);                                      // 5
    {   // 6
        int grid = (total4 + 255) / 256;
        final_kernel<<<grid, 256>>>(x, gamma, beta, out, total4, 1.0f / (float)n_nodes);
    }
}